// round 6
// baseline (speedup 1.0000x reference)
#include <cuda_runtime.h>
#include <cuda_bf16.h>
#include <math.h>
#include <stdint.h>

#define BB 64
#define TOK 64
#define NTK 456
#define LL 457
#define DD 256
#define HH 8
#define HD 32
#define NLAYER 4
#define FFD 1024
#define MM (BB*LL)          // 29248
#define MMP 29312           // padded to multiple of 128

#define WSTRIDE 720896      // per-layer elems in split weight buffer
#define OFF_QKV 0
#define OFF_FF1 196608
#define OFF_FF2 458752

// ---------------- device scratch ----------------
__device__ float g_x   [(size_t)MMP*DD];
__device__ float g_tmp [(size_t)MMP*DD];
__device__ float g_hsc [MM];
// bf16 hi/lo planes
__device__ __nv_bfloat16 g_xh[(size_t)MMP*DD],   g_xl[(size_t)MMP*DD];
__device__ __nv_bfloat16 g_fh[(size_t)MMP*FFD],  g_fl[(size_t)MMP*FFD];
__device__ __nv_bfloat16 g_qvh[(size_t)MMP*768], g_qvl[(size_t)MMP*768];
__device__ __nv_bfloat16 g_wh[(size_t)NLAYER*WSTRIDE], g_wl[(size_t)NLAYER*WSTRIDE];

// ---------------- helpers ----------------
__device__ __forceinline__ void bsplit2(float a, float b,
                                        __nv_bfloat162& hi, __nv_bfloat162& lo)
{
    hi = __floats2bfloat162_rn(a, b);
    lo = __floats2bfloat162_rn(a - __bfloat162float(hi.x),
                               b - __bfloat162float(hi.y));
}

__device__ __forceinline__ void packsplit(float a, float b, uint32_t& h, uint32_t& l)
{
    __nv_bfloat162 hi, lo;
    bsplit2(a, b, hi, lo);
    h = *reinterpret_cast<uint32_t*>(&hi);
    l = *reinterpret_cast<uint32_t*>(&lo);
}

#define MMA16816(d, a0,a1,a2,a3, b0,b1) \
  asm volatile("mma.sync.aligned.m16n8k16.row.col.f32.bf16.bf16.f32 " \
    "{%0,%1,%2,%3}, {%4,%5,%6,%7}, {%8,%9}, {%0,%1,%2,%3};\n" \
    : "+f"(d[0]), "+f"(d[1]), "+f"(d[2]), "+f"(d[3]) \
    : "r"(a0), "r"(a1), "r"(a2), "r"(a3), "r"(b0), "r"(b1))

// ---------------- weight split + transpose: W[K][N] -> Wt planes [N][K] ----------------
__global__ __launch_bounds__(256) void k_wsplit(
    const float* __restrict__ W, int K, int N, size_t out_base)
{
    __shared__ float t[32][33];
    int l = blockIdx.z;
    const float* Wp = W + (size_t)l*K*N;
    int n0 = blockIdx.x*32, k0 = blockIdx.y*32;
    int tx = threadIdx.x & 31, ty = threadIdx.x >> 5;
    #pragma unroll
    for (int i = ty; i < 32; i += 8)
        t[i][tx] = Wp[(size_t)(k0+i)*N + n0 + tx];
    __syncthreads();
    #pragma unroll
    for (int i = ty; i < 32; i += 8) {
        float v = t[tx][i];   // = W[k0+tx][n0+i]
        size_t o = out_base + (size_t)l*WSTRIDE + (size_t)(n0+i)*K + (k0+tx);
        __nv_bfloat16 h = __float2bfloat16(v);
        g_wh[o] = h;
        g_wl[o] = __float2bfloat16(v - __bfloat162float(h));
    }
}

// ---------------- input projection + CLS (also emits bf16 planes) ----------------
__global__ __launch_bounds__(256) void k_input(
    const float* __restrict__ gene, const float* __restrict__ coords,
    const float* __restrict__ w_in, const float* __restrict__ b_in,
    const float* __restrict__ w_cls, const float* __restrict__ b_cls)
{
    int row = blockIdx.x;
    int b = row / LL, l = row % LL;
    int d = threadIdx.x;
    size_t off = (size_t)row*DD + d;
    float acc;
    if (l == 0) {
        acc = b_cls[d];
        #pragma unroll
        for (int k = 0; k < 3; k++) acc += coords[b*3 + k] * w_cls[k*DD + d];
    } else {
        __shared__ float sg[TOK];
        if (d < TOK) sg[d] = gene[(size_t)b*(NTK*TOK) + (size_t)(l-1)*TOK + d];
        __syncthreads();
        float a0 = b_in[d], a1 = 0.f;
        #pragma unroll 8
        for (int k = 0; k < TOK; k += 2) {
            a0 += sg[k]   * w_in[k*DD + d];
            a1 += sg[k+1] * w_in[(k+1)*DD + d];
        }
        acc = a0 + a1;
    }
    g_x[off] = acc;
    __nv_bfloat16 h = __float2bfloat16(acc);
    g_xh[off] = h;
    g_xl[off] = __float2bfloat16(acc - __bfloat162float(h));
}

// ---------------- bf16x3 tensor-core GEMM ----------------
// C[M,N] = A[M,K] @ W[K,N] + bias. Block tile 128x64, warp tile 32x32, KB=32.
// sel 0: A=x planes,   C -> qkv planes (N=768, K=256)
// sel 1: A=x planes,   C -> relu -> ffh planes (N=1024,K=256)
// sel 2: A=ffh planes, C=g_tmp fp32 (N=256, K=1024)
__global__ __launch_bounds__(256) void k_gemm_mma(
    int sel, size_t woff, const float* __restrict__ bias, int N, int K)
{
    __shared__ uint32_t AshH[128*20], AshL[128*20];   // [m][k-pair], pitch 20 words
    __shared__ uint32_t BshH[64*20],  BshL[64*20];    // [n][k-pair]

    const __nv_bfloat16 *Ah, *Al;
    if (sel == 2) { Ah = g_fh; Al = g_fl; }
    else          { Ah = g_xh; Al = g_xl; }

    int tid = threadIdx.x;
    int wid = tid >> 5, lane = tid & 31;
    int g = lane >> 2, c = lane & 3;
    int wm = wid & 3, wn = wid >> 2;
    int bm = blockIdx.y * 128, bn = blockIdx.x * 64;

    float acc[2][4][4] = {};

    for (int k0 = 0; k0 < K; k0 += 32) {
        #pragma unroll
        for (int e = 0; e < 2; e++) {
            int idx = tid + e*256;
            int m = idx >> 2, q = idx & 3;
            size_t go = (size_t)(bm+m)*K + k0 + q*8;
            *reinterpret_cast<uint4*>(AshH + m*20 + q*4) =
                *reinterpret_cast<const uint4*>(Ah + go);
            *reinterpret_cast<uint4*>(AshL + m*20 + q*4) =
                *reinterpret_cast<const uint4*>(Al + go);
        }
        {
            int n = tid >> 2, q = tid & 3;
            size_t go = woff + (size_t)(bn+n)*K + k0 + q*8;
            *reinterpret_cast<uint4*>(BshH + n*20 + q*4) =
                *reinterpret_cast<const uint4*>(g_wh + go);
            *reinterpret_cast<uint4*>(BshL + n*20 + q*4) =
                *reinterpret_cast<const uint4*>(g_wl + go);
        }
        __syncthreads();

        #pragma unroll
        for (int ks = 0; ks < 2; ks++) {
            uint32_t ah[2][4], al[2][4], bh[4][2], bl[4][2];
            #pragma unroll
            for (int mt = 0; mt < 2; mt++) {
                int m = wm*32 + mt*16 + g;
                int w0 = m*20 + ks*8 + c;
                int w1 = (m+8)*20 + ks*8 + c;
                ah[mt][0] = AshH[w0];   ah[mt][1] = AshH[w1];
                ah[mt][2] = AshH[w0+4]; ah[mt][3] = AshH[w1+4];
                al[mt][0] = AshL[w0];   al[mt][1] = AshL[w1];
                al[mt][2] = AshL[w0+4]; al[mt][3] = AshL[w1+4];
            }
            #pragma unroll
            for (int nt = 0; nt < 4; nt++) {
                int n = wn*32 + nt*8 + g;
                int w0 = n*20 + ks*8 + c;
                bh[nt][0] = BshH[w0]; bh[nt][1] = BshH[w0+4];
                bl[nt][0] = BshL[w0]; bl[nt][1] = BshL[w0+4];
            }
            #pragma unroll
            for (int mt = 0; mt < 2; mt++)
                #pragma unroll
                for (int nt = 0; nt < 4; nt++) {
                    MMA16816(acc[mt][nt], ah[mt][0],ah[mt][1],ah[mt][2],ah[mt][3],
                             bh[nt][0], bh[nt][1]);
                    MMA16816(acc[mt][nt], ah[mt][0],ah[mt][1],ah[mt][2],ah[mt][3],
                             bl[nt][0], bl[nt][1]);
                    MMA16816(acc[mt][nt], al[mt][0],al[mt][1],al[mt][2],al[mt][3],
                             bh[nt][0], bh[nt][1]);
                }
        }
        __syncthreads();
    }

    #pragma unroll
    for (int mt = 0; mt < 2; mt++) {
        int r0 = bm + wm*32 + mt*16 + g;
        #pragma unroll
        for (int nt = 0; nt < 4; nt++) {
            int cb = bn + wn*32 + nt*8 + 2*c;
            float2 bv = *reinterpret_cast<const float2*>(&bias[cb]);
            float v00 = acc[mt][nt][0] + bv.x, v01 = acc[mt][nt][1] + bv.y;
            float v10 = acc[mt][nt][2] + bv.x, v11 = acc[mt][nt][3] + bv.y;
            size_t o0 = (size_t)r0*N + cb;
            size_t o1 = (size_t)(r0+8)*N + cb;
            if (sel == 2) {
                *reinterpret_cast<float2*>(g_tmp + o0) = make_float2(v00, v01);
                *reinterpret_cast<float2*>(g_tmp + o1) = make_float2(v10, v11);
            } else {
                __nv_bfloat16 *H, *L;
                if (sel == 1) {
                    v00 = fmaxf(v00, 0.f); v01 = fmaxf(v01, 0.f);
                    v10 = fmaxf(v10, 0.f); v11 = fmaxf(v11, 0.f);
                    H = g_fh; L = g_fl;
                } else { H = g_qvh; L = g_qvl; }
                __nv_bfloat162 hi, lo;
                bsplit2(v00, v01, hi, lo);
                *reinterpret_cast<__nv_bfloat162*>(H + o0) = hi;
                *reinterpret_cast<__nv_bfloat162*>(L + o0) = lo;
                bsplit2(v10, v11, hi, lo);
                *reinterpret_cast<__nv_bfloat162*>(H + o1) = hi;
                *reinterpret_cast<__nv_bfloat162*>(L + o1) = lo;
            }
        }
    }
}

// ---------------- flash attention, bf16x3 tensor-core, register-resident P ----------------
// block = 128 q-rows x (b,h). 8 warps, each 16 q-rows. j chunk = 64.
__global__ __launch_bounds__(256) void k_attn()
{
    __shared__ uint32_t KsH[64*20], KsL[64*20];   // K [j][d-pair] pitch 20 words
    __shared__ uint32_t VtH[32*36], VtL[32*36];   // V^T [d][j-pair] pitch 36 words

    int gz = blockIdx.y;
    int b = gz >> 3, h = gz & 7;
    int qi0 = blockIdx.x * 128;
    int tid = threadIdx.x;
    int wq = tid >> 5, lane = tid & 31;
    int g = lane >> 2, c = lane & 3;

    const float slope = (h < 4) ? 1.0f : 0.5f;
    const float scale = 0.17677669529663689f;   // 1/sqrt(32)

    // Q fragments (rows qi0+wq*16+g / +8), hi & lo
    uint32_t qh[2][4], ql[2][4];
    {
        size_t r0 = ((size_t)b*LL + qi0 + wq*16 + g)*768 + h*HD;
        const __nv_bfloat16* ph = g_qvh + r0;
        const __nv_bfloat16* pl = g_qvl + r0;
        #pragma unroll
        for (int kt = 0; kt < 2; kt++) {
            qh[kt][0] = *(const uint32_t*)(ph + 16*kt + 2*c);
            qh[kt][1] = *(const uint32_t*)(ph + 8*768 + 16*kt + 2*c);
            qh[kt][2] = *(const uint32_t*)(ph + 16*kt + 2*c + 8);
            qh[kt][3] = *(const uint32_t*)(ph + 8*768 + 16*kt + 2*c + 8);
            ql[kt][0] = *(const uint32_t*)(pl + 16*kt + 2*c);
            ql[kt][1] = *(const uint32_t*)(pl + 8*768 + 16*kt + 2*c);
            ql[kt][2] = *(const uint32_t*)(pl + 16*kt + 2*c + 8);
            ql[kt][3] = *(const uint32_t*)(pl + 8*768 + 16*kt + 2*c + 8);
        }
    }

    float oacc[4][4] = {};
    float m_run[2] = {-1e30f, -1e30f};
    float s_run[2] = {0.f, 0.f};

    for (int j0 = 0; j0 < LL; j0 += 64) {
        __syncthreads();
        // load K tile + transposed V tile (hi & lo planes)
        {
            int j = tid >> 2, q = tid & 3;
            size_t krow = ((size_t)b*LL + j0 + j)*768 + 256 + h*HD;
            *reinterpret_cast<uint4*>(KsH + j*20 + q*4) =
                *reinterpret_cast<const uint4*>(g_qvh + krow + q*8);
            *reinterpret_cast<uint4*>(KsL + j*20 + q*4) =
                *reinterpret_cast<const uint4*>(g_qvl + krow + q*8);
            uint4 vh = *reinterpret_cast<const uint4*>(g_qvh + krow + 256 + q*8);
            uint4 vl = *reinterpret_cast<const uint4*>(g_qvl + krow + 256 + q*8);
            const __nv_bfloat16* eh = (const __nv_bfloat16*)&vh;
            const __nv_bfloat16* el = (const __nv_bfloat16*)&vl;
            #pragma unroll
            for (int i = 0; i < 8; i++) {
                ((__nv_bfloat16*)VtH)[(q*8+i)*72 + j] = eh[i];
                ((__nv_bfloat16*)VtL)[(q*8+i)*72 + j] = el[i];
            }
        }
        __syncthreads();

        // S = Q K^T (bf16x3)
        float sacc[8][4] = {};
        #pragma unroll
        for (int nt = 0; nt < 8; nt++) {
            int jrow = nt*8 + g;
            #pragma unroll
            for (int kt = 0; kt < 2; kt++) {
                uint32_t bh0 = KsH[jrow*20 + kt*8 + c];
                uint32_t bh1 = KsH[jrow*20 + kt*8 + c + 4];
                uint32_t bl0 = KsL[jrow*20 + kt*8 + c];
                uint32_t bl1 = KsL[jrow*20 + kt*8 + c + 4];
                MMA16816(sacc[nt], qh[kt][0],qh[kt][1],qh[kt][2],qh[kt][3], bh0, bh1);
                MMA16816(sacc[nt], qh[kt][0],qh[kt][1],qh[kt][2],qh[kt][3], bl0, bl1);
                MMA16816(sacc[nt], ql[kt][0],ql[kt][1],ql[kt][2],ql[kt][3], bh0, bh1);
            }
        }

        // online softmax on register fragments
        float corr[2];
        #pragma unroll
        for (int r = 0; r < 2; r++) {
            int qi = qi0 + wq*16 + g + r*8;
            float mloc = -1e30f;
            #pragma unroll
            for (int nt = 0; nt < 8; nt++) {
                #pragma unroll
                for (int e = 0; e < 2; e++) {
                    int kj = j0 + nt*8 + 2*c + e;
                    float v = sacc[nt][r*2+e]*scale - slope*fabsf((float)(qi - kj));
                    if (kj >= LL) v = -1e30f;
                    sacc[nt][r*2+e] = v;
                    mloc = fmaxf(mloc, v);
                }
            }
            mloc = fmaxf(mloc, __shfl_xor_sync(0xffffffffu, mloc, 1));
            mloc = fmaxf(mloc, __shfl_xor_sync(0xffffffffu, mloc, 2));
            float m_new = fmaxf(m_run[r], mloc);
            corr[r] = __expf(m_run[r] - m_new);
            float rs = 0.f;
            #pragma unroll
            for (int nt = 0; nt < 8; nt++) {
                #pragma unroll
                for (int e = 0; e < 2; e++) {
                    float p = __expf(sacc[nt][r*2+e] - m_new);
                    sacc[nt][r*2+e] = p;
                    rs += p;
                }
            }
            rs += __shfl_xor_sync(0xffffffffu, rs, 1);
            rs += __shfl_xor_sync(0xffffffffu, rs, 2);
            s_run[r] = s_run[r]*corr[r] + rs;
            m_run[r] = m_new;
        }
        #pragma unroll
        for (int nt = 0; nt < 4; nt++) {
            oacc[nt][0] *= corr[0]; oacc[nt][1] *= corr[0];
            oacc[nt][2] *= corr[1]; oacc[nt][3] *= corr[1];
        }

        // O += P V  (P packed from S accumulators, bf16x3)
        #pragma unroll
        for (int kt = 0; kt < 4; kt++) {
            uint32_t pah[4], pal[4];
            packsplit(sacc[2*kt][0],   sacc[2*kt][1],   pah[0], pal[0]);
            packsplit(sacc[2*kt][2],   sacc[2*kt][3],   pah[1], pal[1]);
            packsplit(sacc[2*kt+1][0], sacc[2*kt+1][1], pah[2], pal[2]);
            packsplit(sacc[2*kt+1][2], sacc[2*kt+1][3], pah[3], pal[3]);
            #pragma unroll
            for (int nt = 0; nt < 4; nt++) {
                int drow = nt*8 + g;
                uint32_t bh0 = VtH[drow*36 + kt*8 + c];
                uint32_t bh1 = VtH[drow*36 + kt*8 + c + 4];
                uint32_t bl0 = VtL[drow*36 + kt*8 + c];
                uint32_t bl1 = VtL[drow*36 + kt*8 + c + 4];
                MMA16816(oacc[nt], pah[0],pah[1],pah[2],pah[3], bh0, bh1);
                MMA16816(oacc[nt], pah[0],pah[1],pah[2],pah[3], bl0, bl1);
                MMA16816(oacc[nt], pal[0],pal[1],pal[2],pal[3], bh0, bh1);
            }
        }
    }

    // store O
    float inv0 = 1.0f / s_run[0];
    float inv1 = 1.0f / s_run[1];
    int qi = qi0 + wq*16 + g;
    if (qi < LL) {
        float* o = g_tmp + ((size_t)b*LL + qi)*DD + h*HD;
        #pragma unroll
        for (int nt = 0; nt < 4; nt++)
            *reinterpret_cast<float2*>(o + nt*8 + 2*c) =
                make_float2(oacc[nt][0]*inv0, oacc[nt][1]*inv0);
    }
    if (qi + 8 < LL) {
        float* o = g_tmp + ((size_t)b*LL + qi + 8)*DD + h*HD;
        #pragma unroll
        for (int nt = 0; nt < 4; nt++)
            *reinterpret_cast<float2*>(o + nt*8 + 2*c) =
                make_float2(oacc[nt][2]*inv1, oacc[nt][3]*inv1);
    }
}

// ---------------- x = LN(x + tmp), warp-per-row, optional bf16 plane emit ----------------
__global__ __launch_bounds__(256) void k_addln(
    const float* __restrict__ gamma, const float* __restrict__ beta, int planes)
{
    int w = threadIdx.x >> 5, lane = threadIdx.x & 31;
    int row = blockIdx.x*8 + w;
    size_t base = (size_t)row*DD + lane*4;

    float4 a0 = *reinterpret_cast<const float4*>(&g_x[base]);
    float4 a1 = *reinterpret_cast<const float4*>(&g_x[base+128]);
    float4 t0 = *reinterpret_cast<const float4*>(&g_tmp[base]);
    float4 t1 = *reinterpret_cast<const float4*>(&g_tmp[base+128]);
    float v[8] = {a0.x+t0.x, a0.y+t0.y, a0.z+t0.z, a0.w+t0.w,
                  a1.x+t1.x, a1.y+t1.y, a1.z+t1.z, a1.w+t1.w};
    float s = 0.f, s2 = 0.f;
    #pragma unroll
    for (int i = 0; i < 8; i++) { s += v[i]; s2 += v[i]*v[i]; }
    #pragma unroll
    for (int off = 16; off > 0; off >>= 1) {
        s  += __shfl_xor_sync(0xffffffffu, s,  off);
        s2 += __shfl_xor_sync(0xffffffffu, s2, off);
    }
    float mean = s * (1.0f/256.0f);
    float var  = s2 * (1.0f/256.0f) - mean*mean;
    float inv  = rsqrtf(var + 1e-5f);

    float4 gg0 = *reinterpret_cast<const float4*>(&gamma[lane*4]);
    float4 gg1 = *reinterpret_cast<const float4*>(&gamma[128 + lane*4]);
    float4 bb0 = *reinterpret_cast<const float4*>(&beta[lane*4]);
    float4 bb1 = *reinterpret_cast<const float4*>(&beta[128 + lane*4]);
    float gv[8] = {gg0.x,gg0.y,gg0.z,gg0.w, gg1.x,gg1.y,gg1.z,gg1.w};
    float bv[8] = {bb0.x,bb0.y,bb0.z,bb0.w, bb1.x,bb1.y,bb1.z,bb1.w};
    float y[8];
    #pragma unroll
    for (int i = 0; i < 8; i++) y[i] = (v[i]-mean)*inv*gv[i] + bv[i];

    *reinterpret_cast<float4*>(&g_x[base])     = make_float4(y[0],y[1],y[2],y[3]);
    *reinterpret_cast<float4*>(&g_x[base+128]) = make_float4(y[4],y[5],y[6],y[7]);
    if (planes) {
        #pragma unroll
        for (int p = 0; p < 4; p++) {
            size_t o = base + (p>>1)*128 + (p&1)*2;
            int i = p*2;
            __nv_bfloat162 hi, lo;
            bsplit2(y[i], y[i+1], hi, lo);
            *reinterpret_cast<__nv_bfloat162*>(g_xh + o) = hi;
            *reinterpret_cast<__nv_bfloat162*>(g_xl + o) = lo;
        }
    }
}

// ---------------- head ----------------
__global__ __launch_bounds__(256) void k_head(
    const float* __restrict__ th1_w, const float* __restrict__ th1_b,
    const float* __restrict__ bn_g,  const float* __restrict__ bn_b,
    const float* __restrict__ th2_w, const float* __restrict__ th2_b)
{
    __shared__ float sx[8][256];
    __shared__ float sw1[256*32];
    int tid = threadIdx.x;
    int w = tid >> 5, lane = tid & 31;
    int row0 = blockIdx.x * 8;
    #pragma unroll
    for (int e = 0; e < 32; e++) sw1[tid + e*256] = th1_w[tid + e*256];
    #pragma unroll
    for (int e = 0; e < 8; e++) {
        int idx = tid + e*256;
        int r = idx >> 8, c = idx & 255;
        int row = row0 + r;
        sx[r][c] = (row < MM) ? g_x[(size_t)row*DD + c] : 0.f;
    }
    __syncthreads();
    int row = row0 + w;
    if (row < MM) {
        float acc = th1_b[lane];
        #pragma unroll 8
        for (int k = 0; k < 256; k++) acc += sx[w][k] * sw1[k*32 + lane];
        acc = acc * (bn_g[lane] * rsqrtf(1.0f + 1e-5f)) + bn_b[lane];
        float t = tanhf(0.7978845608028654f * (acc + 0.044715f*acc*acc*acc));
        float ge = 0.5f * acc * (1.0f + t);
        float ps = ge * th2_w[lane];
        #pragma unroll
        for (int s = 16; s > 0; s >>= 1) ps += __shfl_xor_sync(0xffffffffu, ps, s);
        if (lane == 0) g_hsc[row] = ps + th2_b[0];
    }
}

// ---------------- softmax over L + pooled output ----------------
__global__ __launch_bounds__(256) void k_pool(float* __restrict__ out)
{
    int b = blockIdx.x, tid = threadIdx.x;
    __shared__ float wv[LL];
    __shared__ float red[256];
    float v[2];
    #pragma unroll
    for (int i = 0; i < 2; i++) {
        int l = tid + i*256;
        v[i] = (l < LL) ? g_hsc[b*LL + l] : -1e30f;
    }
    float m = fmaxf(v[0], v[1]);
    red[tid] = m; __syncthreads();
    for (int s = 128; s > 0; s >>= 1) { if (tid < s) red[tid] = fmaxf(red[tid], red[tid+s]); __syncthreads(); }
    m = red[0]; __syncthreads();
    float sum = 0.f;
    #pragma unroll
    for (int i = 0; i < 2; i++) { v[i] = __expf(v[i] - m); sum += v[i]; }
    red[tid] = sum; __syncthreads();
    for (int s = 128; s > 0; s >>= 1) { if (tid < s) red[tid] += red[tid+s]; __syncthreads(); }
    float inv = 1.0f / red[0];
    #pragma unroll
    for (int i = 0; i < 2; i++) {
        int l = tid + i*256;
        if (l < LL) wv[l] = v[i] * inv;
    }
    __syncthreads();
    float acc = 0.f;
    const float* xb = g_x + (size_t)b*LL*DD;
    for (int l = 0; l < LL; l++) acc += wv[l] * xb[(size_t)l*DD + tid];
    out[b*DD + tid] = acc;
}

// ---------------- launcher ----------------
extern "C" void kernel_launch(void* const* d_in, const int* in_sizes, int n_in,
                              void* d_out, int out_size)
{
    const float* gene   = (const float*)d_in[0];
    const float* coords = (const float*)d_in[1];
    const float* w_in   = (const float*)d_in[2];
    const float* b_in   = (const float*)d_in[3];
    const float* w_cls  = (const float*)d_in[4];
    const float* b_cls  = (const float*)d_in[5];
    const float* qkv_w  = (const float*)d_in[6];
    const float* qkv_b  = (const float*)d_in[7];
    const float* ln1_g  = (const float*)d_in[8];
    const float* ln1_b  = (const float*)d_in[9];
    const float* ffn_w1 = (const float*)d_in[10];
    const float* ffn_b1 = (const float*)d_in[11];
    const float* ffn_w2 = (const float*)d_in[12];
    const float* ffn_b2 = (const float*)d_in[13];
    const float* ln2_g  = (const float*)d_in[14];
    const float* ln2_b  = (const float*)d_in[15];
    const float* th1_w  = (const float*)d_in[16];
    const float* th1_b  = (const float*)d_in[17];
    const float* bn_g   = (const float*)d_in[18];
    const float* bn_b   = (const float*)d_in[19];
    const float* th2_w  = (const float*)d_in[20];
    const float* th2_b  = (const float*)d_in[21];
    float* out = (float*)d_out;

    k_wsplit<<<dim3(768/32, 256/32, NLAYER), 256>>>(qkv_w,  256, 768,  OFF_QKV);
    k_wsplit<<<dim3(1024/32, 256/32, NLAYER), 256>>>(ffn_w1, 256, 1024, OFF_FF1);
    k_wsplit<<<dim3(256/32, 1024/32, NLAYER), 256>>>(ffn_w2, 1024, 256, OFF_FF2);

    k_input<<<BB*LL, 256>>>(gene, coords, w_in, b_in, w_cls, b_cls);

    for (int l = 0; l < NLAYER; l++) {
        size_t wbase = (size_t)l*WSTRIDE;
        k_gemm_mma<<<dim3(768/64, MMP/128), 256>>>(0, wbase + OFF_QKV,
                                                   qkv_b + (size_t)l*768, 768, 256);
        k_attn<<<dim3(4, BB*HH), 256>>>();
        k_addln<<<MM/8, 256>>>(ln1_g + (size_t)l*DD, ln1_b + (size_t)l*DD, 1);
        k_gemm_mma<<<dim3(1024/64, MMP/128), 256>>>(1, wbase + OFF_FF1,
                                                    ffn_b1 + (size_t)l*FFD, 1024, 256);
        k_gemm_mma<<<dim3(256/64, MMP/128), 256>>>(2, wbase + OFF_FF2,
                                                   ffn_b2 + (size_t)l*DD, 256, 1024);
        k_addln<<<MM/8, 256>>>(ln2_g + (size_t)l*DD, ln2_b + (size_t)l*DD, (l < 3) ? 1 : 0);
    }

    k_head<<<(MM + 7)/8, 256>>>(th1_w, th1_b, bn_g, bn_b, th2_w, th2_b);
    k_pool<<<BB, 256>>>(out);
}

// round 12
// speedup vs baseline: 1.2387x; 1.2387x over previous
#include <cuda_runtime.h>
#include <cuda_bf16.h>
#include <math.h>
#include <stdint.h>

#define BB 64
#define TOK 64
#define NTK 456
#define LL 457
#define DD 256
#define HH 8
#define HD 32
#define NLAYER 4
#define FFD 1024
#define MM (BB*LL)          // 29248
#define MMP 29312           // padded to multiple of 128

#define WSTRIDE 720896      // per-layer elems in split weight buffer
#define OFF_QKV 0
#define OFF_FF1 196608
#define OFF_FF2 458752

// ---------------- device scratch ----------------
__device__ float g_x   [(size_t)MMP*DD];
__device__ float g_tmp [(size_t)MMP*DD];
__device__ float g_hsc [MM];
// bf16 hi/lo planes
__device__ __nv_bfloat16 g_xh[(size_t)MMP*DD],   g_xl[(size_t)MMP*DD];
__device__ __nv_bfloat16 g_fh[(size_t)MMP*FFD],  g_fl[(size_t)MMP*FFD];
__device__ __nv_bfloat16 g_qvh[(size_t)MMP*768], g_qvl[(size_t)MMP*768];
__device__ __nv_bfloat16 g_wh[(size_t)NLAYER*WSTRIDE], g_wl[(size_t)NLAYER*WSTRIDE];

// ---------------- helpers ----------------
__device__ __forceinline__ void bsplit2(float a, float b,
                                        __nv_bfloat162& hi, __nv_bfloat162& lo)
{
    hi = __floats2bfloat162_rn(a, b);
    lo = __floats2bfloat162_rn(a - __bfloat162float(hi.x),
                               b - __bfloat162float(hi.y));
}

__device__ __forceinline__ void packsplit(float a, float b, uint32_t& h, uint32_t& l)
{
    __nv_bfloat162 hi, lo;
    bsplit2(a, b, hi, lo);
    h = *reinterpret_cast<uint32_t*>(&hi);
    l = *reinterpret_cast<uint32_t*>(&lo);
}

__device__ __forceinline__ uint32_t smem_u32(const void* p) {
    uint32_t a;
    asm("{ .reg .u64 t; cvta.to.shared.u64 t, %1; cvt.u32.u64 %0, t; }"
        : "=r"(a) : "l"(p));
    return a;
}

#define MMA16816(d, a0,a1,a2,a3, b0,b1) \
  asm volatile("mma.sync.aligned.m16n8k16.row.col.f32.bf16.bf16.f32 " \
    "{%0,%1,%2,%3}, {%4,%5,%6,%7}, {%8,%9}, {%0,%1,%2,%3};\n" \
    : "+f"(d[0]), "+f"(d[1]), "+f"(d[2]), "+f"(d[3]) \
    : "r"(a0), "r"(a1), "r"(a2), "r"(a3), "r"(b0), "r"(b1))

#define CP_ASYNC16(dst, src) \
  asm volatile("cp.async.cg.shared.global [%0], [%1], 16;\n" \
    :: "r"(dst), "l"(src) : "memory")
#define CP_COMMIT  asm volatile("cp.async.commit_group;\n" ::: "memory")
#define CP_WAIT1   asm volatile("cp.async.wait_group 1;\n" ::: "memory")

#define LDMX4(r0,r1,r2,r3, addr) \
  asm volatile("ldmatrix.sync.aligned.m8n8.x4.shared.b16 {%0,%1,%2,%3}, [%4];" \
    : "=r"(r0),"=r"(r1),"=r"(r2),"=r"(r3) : "r"(addr))
#define LDMX2(r0,r1, addr) \
  asm volatile("ldmatrix.sync.aligned.m8n8.x2.shared.b16 {%0,%1}, [%2];" \
    : "=r"(r0),"=r"(r1) : "r"(addr))
#define LDMX2T(r0,r1, addr) \
  asm volatile("ldmatrix.sync.aligned.m8n8.x2.trans.shared.b16 {%0,%1}, [%2];" \
    : "=r"(r0),"=r"(r1) : "r"(addr))

// ---------------- weight split + transpose: W[K][N] -> Wt planes [N][K] ----------------
__global__ __launch_bounds__(256) void k_wsplit(
    const float* __restrict__ W, int K, int N, size_t out_base)
{
    __shared__ float t[32][33];
    int l = blockIdx.z;
    const float* Wp = W + (size_t)l*K*N;
    int n0 = blockIdx.x*32, k0 = blockIdx.y*32;
    int tx = threadIdx.x & 31, ty = threadIdx.x >> 5;
    #pragma unroll
    for (int i = ty; i < 32; i += 8)
        t[i][tx] = Wp[(size_t)(k0+i)*N + n0 + tx];
    __syncthreads();
    #pragma unroll
    for (int i = ty; i < 32; i += 8) {
        float v = t[tx][i];   // = W[k0+tx][n0+i]
        size_t o = out_base + (size_t)l*WSTRIDE + (size_t)(n0+i)*K + (k0+tx);
        __nv_bfloat16 h = __float2bfloat16(v);
        g_wh[o] = h;
        g_wl[o] = __float2bfloat16(v - __bfloat162float(h));
    }
}

// ---------------- input projection + CLS (also emits bf16 planes) ----------------
__global__ __launch_bounds__(256) void k_input(
    const float* __restrict__ gene, const float* __restrict__ coords,
    const float* __restrict__ w_in, const float* __restrict__ b_in,
    const float* __restrict__ w_cls, const float* __restrict__ b_cls)
{
    int row = blockIdx.x;
    int b = row / LL, l = row % LL;
    int d = threadIdx.x;
    size_t off = (size_t)row*DD + d;
    float acc;
    if (l == 0) {
        acc = b_cls[d];
        #pragma unroll
        for (int k = 0; k < 3; k++) acc += coords[b*3 + k] * w_cls[k*DD + d];
    } else {
        __shared__ float sg[TOK];
        if (d < TOK) sg[d] = gene[(size_t)b*(NTK*TOK) + (size_t)(l-1)*TOK + d];
        __syncthreads();
        float a0 = b_in[d], a1 = 0.f;
        #pragma unroll 8
        for (int k = 0; k < TOK; k += 2) {
            a0 += sg[k]   * w_in[k*DD + d];
            a1 += sg[k+1] * w_in[(k+1)*DD + d];
        }
        acc = a0 + a1;
    }
    g_x[off] = acc;
    __nv_bfloat16 h = __float2bfloat16(acc);
    g_xh[off] = h;
    g_xl[off] = __float2bfloat16(acc - __bfloat162float(h));
}

// ---------------- bf16x3 tensor-core GEMM, cp.async double-buffered ----------------
// C[M,N] = A[M,K] @ W[K,N] + bias. Block tile 128x64, warp tile 32x32, KB=32.
// sel 0: A=x planes,   C -> qkv planes (N=768, K=256)
// sel 1: A=x planes,   C -> relu -> ffh planes (N=1024, K=256)
// sel 2: A=ffh planes, C=g_tmp fp32 (N=256, K=1024)
// smem stage layout (words): AH@0 (2560), AL@2560, BH@5120 (1280), BL@6400; stride 7680
#define GSTG 7680
__global__ __launch_bounds__(256) void k_gemm_mma(
    int sel, size_t woff, const float* __restrict__ bias, int N, int K)
{
    extern __shared__ __align__(16) uint32_t sm[];

    const __nv_bfloat16 *Ah, *Al;
    if (sel == 2) { Ah = g_fh; Al = g_fl; } else { Ah = g_xh; Al = g_xl; }

    int tid = threadIdx.x;
    int wid = tid >> 5, lane = tid & 31;
    int g = lane >> 2, c = lane & 3;
    int wm = wid & 3, wn = wid >> 2;
    int bm = blockIdx.y * 128, bn = blockIdx.x * 64;
    uint32_t sbase = smem_u32(sm);

    float acc[2][4][4] = {};
    const int nch = K >> 5;

    auto issue_loads = [&](int ch, int st) {
        int k0 = ch << 5;
        uint32_t sb = sbase + (uint32_t)st*GSTG*4;
        #pragma unroll
        for (int e = 0; e < 2; e++) {
            int idx = tid + e*256;
            int m = idx >> 2, q = idx & 3;
            uint32_t d = sb + (uint32_t)(m*20 + q*4)*4;
            size_t go = (size_t)(bm + m)*K + k0 + q*8;
            CP_ASYNC16(d,            (const char*)(Ah + go));
            CP_ASYNC16(d + 2560*4,   (const char*)(Al + go));
        }
        {
            int n = tid >> 2, q = tid & 3;
            uint32_t d = sb + (uint32_t)(5120 + n*20 + q*4)*4;
            size_t go = woff + (size_t)(bn + n)*K + k0 + q*8;
            CP_ASYNC16(d,            (const char*)(g_wh + go));
            CP_ASYNC16(d + 1280*4,   (const char*)(g_wl + go));
        }
    };

    issue_loads(0, 0);
    CP_COMMIT;

    int lr = lane & 7, seg = lane >> 3;
    int l16 = lane & 15;

    for (int ch = 0; ch < nch; ch++) {
        if (ch + 1 < nch) issue_loads(ch + 1, (ch + 1) & 1);
        CP_COMMIT;
        CP_WAIT1;
        __syncthreads();

        uint32_t sb = sbase + (uint32_t)(ch & 1)*GSTG*4;
        uint32_t aH = sb, aL = sb + 2560*4, bH = sb + 5120*4, bL = sb + 6400*4;

        #pragma unroll
        for (int ks = 0; ks < 2; ks++) {
            uint32_t ah[2][4], al[2][4], bh[4][2], bl[4][2];
            #pragma unroll
            for (int mt = 0; mt < 2; mt++) {
                int row = wm*32 + mt*16 + lr + (seg & 1)*8;
                uint32_t ad = (uint32_t)(row*80 + ks*32 + (seg >> 1)*16);
                LDMX4(ah[mt][0], ah[mt][1], ah[mt][2], ah[mt][3], aH + ad);
                LDMX4(al[mt][0], al[mt][1], al[mt][2], al[mt][3], aL + ad);
            }
            #pragma unroll
            for (int nt = 0; nt < 4; nt++) {
                int row = wn*32 + nt*8 + (l16 & 7);
                uint32_t bd = (uint32_t)(row*80 + ks*32 + (l16 >> 3)*16);
                LDMX2(bh[nt][0], bh[nt][1], bH + bd);
                LDMX2(bl[nt][0], bl[nt][1], bL + bd);
            }
            #pragma unroll
            for (int mt = 0; mt < 2; mt++)
                #pragma unroll
                for (int nt = 0; nt < 4; nt++) {
                    MMA16816(acc[mt][nt], ah[mt][0],ah[mt][1],ah[mt][2],ah[mt][3],
                             bh[nt][0], bh[nt][1]);
                    MMA16816(acc[mt][nt], ah[mt][0],ah[mt][1],ah[mt][2],ah[mt][3],
                             bl[nt][0], bl[nt][1]);
                    MMA16816(acc[mt][nt], al[mt][0],al[mt][1],al[mt][2],al[mt][3],
                             bh[nt][0], bh[nt][1]);
                }
        }
        __syncthreads();
    }

    #pragma unroll
    for (int mt = 0; mt < 2; mt++) {
        int r0 = bm + wm*32 + mt*16 + g;
        #pragma unroll
        for (int nt = 0; nt < 4; nt++) {
            int cb = bn + wn*32 + nt*8 + 2*c;
            float2 bv = *reinterpret_cast<const float2*>(&bias[cb]);
            float v00 = acc[mt][nt][0] + bv.x, v01 = acc[mt][nt][1] + bv.y;
            float v10 = acc[mt][nt][2] + bv.x, v11 = acc[mt][nt][3] + bv.y;
            size_t o0 = (size_t)r0*N + cb;
            size_t o1 = (size_t)(r0+8)*N + cb;
            if (sel == 2) {
                *reinterpret_cast<float2*>(g_tmp + o0) = make_float2(v00, v01);
                *reinterpret_cast<float2*>(g_tmp + o1) = make_float2(v10, v11);
            } else {
                __nv_bfloat16 *H, *L;
                if (sel == 1) {
                    v00 = fmaxf(v00, 0.f); v01 = fmaxf(v01, 0.f);
                    v10 = fmaxf(v10, 0.f); v11 = fmaxf(v11, 0.f);
                    H = g_fh; L = g_fl;
                } else { H = g_qvh; L = g_qvl; }
                __nv_bfloat162 hi, lo;
                bsplit2(v00, v01, hi, lo);
                *reinterpret_cast<__nv_bfloat162*>(H + o0) = hi;
                *reinterpret_cast<__nv_bfloat162*>(L + o0) = lo;
                bsplit2(v10, v11, hi, lo);
                *reinterpret_cast<__nv_bfloat162*>(H + o1) = hi;
                *reinterpret_cast<__nv_bfloat162*>(L + o1) = lo;
            }
        }
    }
}

// ---------------- flash attention, bf16x3 mma, cp.async double-buffered ----------------
// block = 128 q-rows x (b,h). 8 warps, each 16 q-rows. j chunk = 64. 8 chunks.
__global__ __launch_bounds__(256) void k_attn()
{
    // per stage: KH,KL,VH,VL each 64 rows x 20-word pitch (row = 32 bf16 used)
    __shared__ uint32_t Ks[2][2][64*20];
    __shared__ uint32_t Vs[2][2][64*20];

    int gz = blockIdx.y;
    int b = gz >> 3, h = gz & 7;
    int qi0 = blockIdx.x * 128;
    int tid = threadIdx.x;
    int wq = tid >> 5, lane = tid & 31;
    int g = lane >> 2, c = lane & 3;
    int l16 = lane & 15;

    const float slope = (h < 4) ? 1.0f : 0.5f;
    const float scale = 0.17677669529663689f;   // 1/sqrt(32)

    // Q fragments (rows qi0+wq*16+g / +8), hi & lo
    uint32_t qh[2][4], ql[2][4];
    {
        size_t r0 = ((size_t)b*LL + qi0 + wq*16 + g)*768 + h*HD;
        const __nv_bfloat16* ph = g_qvh + r0;
        const __nv_bfloat16* pl = g_qvl + r0;
        #pragma unroll
        for (int kt = 0; kt < 2; kt++) {
            qh[kt][0] = *(const uint32_t*)(ph + 16*kt + 2*c);
            qh[kt][1] = *(const uint32_t*)(ph + 8*768 + 16*kt + 2*c);
            qh[kt][2] = *(const uint32_t*)(ph + 16*kt + 2*c + 8);
            qh[kt][3] = *(const uint32_t*)(ph + 8*768 + 16*kt + 2*c + 8);
            ql[kt][0] = *(const uint32_t*)(pl + 16*kt + 2*c);
            ql[kt][1] = *(const uint32_t*)(pl + 8*768 + 16*kt + 2*c);
            ql[kt][2] = *(const uint32_t*)(pl + 16*kt + 2*c + 8);
            ql[kt][3] = *(const uint32_t*)(pl + 8*768 + 16*kt + 2*c + 8);
        }
    }

    // per thread load task: one (row j, q) of K and of V (hi+lo each)
    int ldj = tid >> 2, ldq = tid & 3;
    auto issue_loads = [&](int ch, int st) {
        int j0 = ch << 6;
        size_t krow = ((size_t)b*LL + j0 + ldj)*768 + 256 + h*HD + ldq*8;
        uint32_t dk = smem_u32(&Ks[st][0][0]) + (uint32_t)(ldj*20 + ldq*4)*4;
        uint32_t dv = smem_u32(&Vs[st][0][0]) + (uint32_t)(ldj*20 + ldq*4)*4;
        CP_ASYNC16(dk,            (const char*)(g_qvh + krow));
        CP_ASYNC16(dk + 5120,     (const char*)(g_qvl + krow));     // KL plane (+1280 words)
        CP_ASYNC16(dv,            (const char*)(g_qvh + krow + 256));
        CP_ASYNC16(dv + 5120,     (const char*)(g_qvl + krow + 256));
    };

    float oacc[4][4] = {};
    float m_run[2] = {-1e30f, -1e30f};
    float s_run[2] = {0.f, 0.f};

    issue_loads(0, 0);
    CP_COMMIT;

    const int nch = 8;   // ceil(457/64)
    for (int ch = 0; ch < nch; ch++) {
        if (ch + 1 < nch) issue_loads(ch + 1, (ch + 1) & 1);
        CP_COMMIT;
        CP_WAIT1;
        __syncthreads();

        int st = ch & 1;
        int j0 = ch << 6;
        uint32_t kH = smem_u32(&Ks[st][0][0]), kL = kH + 5120;
        uint32_t vH = smem_u32(&Vs[st][0][0]), vL = vH + 5120;

        // S = Q K^T (bf16x3)
        float sacc[8][4] = {};
        #pragma unroll
        for (int nt = 0; nt < 8; nt++) {
            int row = nt*8 + (l16 & 7);
            #pragma unroll
            for (int kt = 0; kt < 2; kt++) {
                uint32_t bd = (uint32_t)(row*80 + kt*32 + (l16 >> 3)*16);
                uint32_t bh0, bh1, bl0, bl1;
                LDMX2(bh0, bh1, kH + bd);
                LDMX2(bl0, bl1, kL + bd);
                MMA16816(sacc[nt], qh[kt][0],qh[kt][1],qh[kt][2],qh[kt][3], bh0, bh1);
                MMA16816(sacc[nt], qh[kt][0],qh[kt][1],qh[kt][2],qh[kt][3], bl0, bl1);
                MMA16816(sacc[nt], ql[kt][0],ql[kt][1],ql[kt][2],ql[kt][3], bh0, bh1);
            }
        }

        // online softmax on register fragments
        float corr[2];
        #pragma unroll
        for (int r = 0; r < 2; r++) {
            int qi = qi0 + wq*16 + g + r*8;
            float mloc = -1e30f;
            #pragma unroll
            for (int nt = 0; nt < 8; nt++) {
                #pragma unroll
                for (int e = 0; e < 2; e++) {
                    int kj = j0 + nt*8 + 2*c + e;
                    float v = sacc[nt][r*2+e]*scale - slope*fabsf((float)(qi - kj));
                    if (kj >= LL) v = -1e30f;
                    sacc[nt][r*2+e] = v;
                    mloc = fmaxf(mloc, v);
                }
            }
            mloc = fmaxf(mloc, __shfl_xor_sync(0xffffffffu, mloc, 1));
            mloc = fmaxf(mloc, __shfl_xor_sync(0xffffffffu, mloc, 2));
            float m_new = fmaxf(m_run[r], mloc);
            corr[r] = __expf(m_run[r] - m_new);
            float rs = 0.f;
            #pragma unroll
            for (int nt = 0; nt < 8; nt++) {
                #pragma unroll
                for (int e = 0; e < 2; e++) {
                    float p = __expf(sacc[nt][r*2+e] - m_new);
                    sacc[nt][r*2+e] = p;
                    rs += p;
                }
            }
            rs += __shfl_xor_sync(0xffffffffu, rs, 1);
            rs += __shfl_xor_sync(0xffffffffu, rs, 2);
            s_run[r] = s_run[r]*corr[r] + rs;
            m_run[r] = m_new;
        }
        #pragma unroll
        for (int nt = 0; nt < 4; nt++) {
            oacc[nt][0] *= corr[0]; oacc[nt][1] *= corr[0];
            oacc[nt][2] *= corr[1]; oacc[nt][3] *= corr[1];
        }

        // O += P V  (P packed from S accumulators; V fragments via ldmatrix.trans)
        #pragma unroll
        for (int kt = 0; kt < 4; kt++) {
            uint32_t pah[4], pal[4];
            packsplit(sacc[2*kt][0],   sacc[2*kt][1],   pah[0], pal[0]);
            packsplit(sacc[2*kt][2],   sacc[2*kt][3],   pah[1], pal[1]);
            packsplit(sacc[2*kt+1][0], sacc[2*kt+1][1], pah[2], pal[2]);
            packsplit(sacc[2*kt+1][2], sacc[2*kt+1][3], pah[3], pal[3]);
            int vrow = kt*16 + (l16 & 7) + (l16 >> 3)*8;
            #pragma unroll
            for (int nt = 0; nt < 4; nt++) {
                uint32_t bd = (uint32_t)(vrow*80 + nt*16);
                uint32_t bh0, bh1, bl0, bl1;
                LDMX2T(bh0, bh1, vH + bd);
                LDMX2T(bl0, bl1, vL + bd);
                MMA16816(oacc[nt], pah[0],pah[1],pah[2],pah[3], bh0, bh1);
                MMA16816(oacc[nt], pah[0],pah[1],pah[2],pah[3], bl0, bl1);
                MMA16816(oacc[nt], pal[0],pal[1],pal[2],pal[3], bh0, bh1);
            }
        }
        __syncthreads();
    }

    // store O
    float inv0 = 1.0f / s_run[0];
    float inv1 = 1.0f / s_run[1];
    int qi = qi0 + wq*16 + g;
    if (qi < LL) {
        float* o = g_tmp + ((size_t)b*LL + qi)*DD + h*HD;
        #pragma unroll
        for (int nt = 0; nt < 4; nt++)
            *reinterpret_cast<float2*>(o + nt*8 + 2*c) =
                make_float2(oacc[nt][0]*inv0, oacc[nt][1]*inv0);
    }
    if (qi + 8 < LL) {
        float* o = g_tmp + ((size_t)b*LL + qi + 8)*DD + h*HD;
        #pragma unroll
        for (int nt = 0; nt < 4; nt++)
            *reinterpret_cast<float2*>(o + nt*8 + 2*c) =
                make_float2(oacc[nt][2]*inv1, oacc[nt][3]*inv1);
    }
}

// ---------------- x = LN(x + tmp), warp-per-row, optional bf16 plane emit ----------------
__global__ __launch_bounds__(256) void k_addln(
    const float* __restrict__ gamma, const float* __restrict__ beta, int planes)
{
    int w = threadIdx.x >> 5, lane = threadIdx.x & 31;
    int row = blockIdx.x*8 + w;
    size_t base = (size_t)row*DD + lane*4;

    float4 a0 = *reinterpret_cast<const float4*>(&g_x[base]);
    float4 a1 = *reinterpret_cast<const float4*>(&g_x[base+128]);
    float4 t0 = *reinterpret_cast<const float4*>(&g_tmp[base]);
    float4 t1 = *reinterpret_cast<const float4*>(&g_tmp[base+128]);
    float v[8] = {a0.x+t0.x, a0.y+t0.y, a0.z+t0.z, a0.w+t0.w,
                  a1.x+t1.x, a1.y+t1.y, a1.z+t1.z, a1.w+t1.w};
    float s = 0.f, s2 = 0.f;
    #pragma unroll
    for (int i = 0; i < 8; i++) { s += v[i]; s2 += v[i]*v[i]; }
    #pragma unroll
    for (int off = 16; off > 0; off >>= 1) {
        s  += __shfl_xor_sync(0xffffffffu, s,  off);
        s2 += __shfl_xor_sync(0xffffffffu, s2, off);
    }
    float mean = s * (1.0f/256.0f);
    float var  = s2 * (1.0f/256.0f) - mean*mean;
    float inv  = rsqrtf(var + 1e-5f);

    float4 gg0 = *reinterpret_cast<const float4*>(&gamma[lane*4]);
    float4 gg1 = *reinterpret_cast<const float4*>(&gamma[128 + lane*4]);
    float4 bb0 = *reinterpret_cast<const float4*>(&beta[lane*4]);
    float4 bb1 = *reinterpret_cast<const float4*>(&beta[128 + lane*4]);
    float gv[8] = {gg0.x,gg0.y,gg0.z,gg0.w, gg1.x,gg1.y,gg1.z,gg1.w};
    float bv[8] = {bb0.x,bb0.y,bb0.z,bb0.w, bb1.x,bb1.y,bb1.z,bb1.w};
    float y[8];
    #pragma unroll
    for (int i = 0; i < 8; i++) y[i] = (v[i]-mean)*inv*gv[i] + bv[i];

    *reinterpret_cast<float4*>(&g_x[base])     = make_float4(y[0],y[1],y[2],y[3]);
    *reinterpret_cast<float4*>(&g_x[base+128]) = make_float4(y[4],y[5],y[6],y[7]);
    if (planes) {
        #pragma unroll
        for (int p = 0; p < 4; p++) {
            size_t o = base + (p>>1)*128 + (p&1)*2;
            int i = p*2;
            __nv_bfloat162 hi, lo;
            bsplit2(y[i], y[i+1], hi, lo);
            *reinterpret_cast<__nv_bfloat162*>(g_xh + o) = hi;
            *reinterpret_cast<__nv_bfloat162*>(g_xl + o) = lo;
        }
    }
}

// ---------------- head ----------------
__global__ __launch_bounds__(256) void k_head(
    const float* __restrict__ th1_w, const float* __restrict__ th1_b,
    const float* __restrict__ bn_g,  const float* __restrict__ bn_b,
    const float* __restrict__ th2_w, const float* __restrict__ th2_b)
{
    __shared__ float sx[8][256];
    __shared__ float sw1[256*32];
    int tid = threadIdx.x;
    int w = tid >> 5, lane = tid & 31;
    int row0 = blockIdx.x * 8;
    #pragma unroll
    for (int e = 0; e < 32; e++) sw1[tid + e*256] = th1_w[tid + e*256];
    #pragma unroll
    for (int e = 0; e < 8; e++) {
        int idx = tid + e*256;
        int r = idx >> 8, c = idx & 255;
        int row = row0 + r;
        sx[r][c] = (row < MM) ? g_x[(size_t)row*DD + c] : 0.f;
    }
    __syncthreads();
    int row = row0 + w;
    if (row < MM) {
        float acc = th1_b[lane];
        #pragma unroll 8
        for (int k = 0; k < 256; k++) acc += sx[w][k] * sw1[k*32 + lane];
        acc = acc * (bn_g[lane] * rsqrtf(1.0f + 1e-5f)) + bn_b[lane];
        float t = tanhf(0.7978845608028654f * (acc + 0.044715f*acc*acc*acc));
        float ge = 0.5f * acc * (1.0f + t);
        float ps = ge * th2_w[lane];
        #pragma unroll
        for (int s = 16; s > 0; s >>= 1) ps += __shfl_xor_sync(0xffffffffu, ps, s);
        if (lane == 0) g_hsc[row] = ps + th2_b[0];
    }
}

// ---------------- softmax over L + pooled output ----------------
__global__ __launch_bounds__(256) void k_pool(float* __restrict__ out)
{
    int b = blockIdx.x, tid = threadIdx.x;
    __shared__ float wv[LL];
    __shared__ float red[256];
    float v[2];
    #pragma unroll
    for (int i = 0; i < 2; i++) {
        int l = tid + i*256;
        v[i] = (l < LL) ? g_hsc[b*LL + l] : -1e30f;
    }
    float m = fmaxf(v[0], v[1]);
    red[tid] = m; __syncthreads();
    for (int s = 128; s > 0; s >>= 1) { if (tid < s) red[tid] = fmaxf(red[tid], red[tid+s]); __syncthreads(); }
    m = red[0]; __syncthreads();
    float sum = 0.f;
    #pragma unroll
    for (int i = 0; i < 2; i++) { v[i] = __expf(v[i] - m); sum += v[i]; }
    red[tid] = sum; __syncthreads();
    for (int s = 128; s > 0; s >>= 1) { if (tid < s) red[tid] += red[tid+s]; __syncthreads(); }
    float inv = 1.0f / red[0];
    #pragma unroll
    for (int i = 0; i < 2; i++) {
        int l = tid + i*256;
        if (l < LL) wv[l] = v[i] * inv;
    }
    __syncthreads();
    float acc = 0.f;
    const float* xb = g_x + (size_t)b*LL*DD;
    for (int l = 0; l < LL; l++) acc += wv[l] * xb[(size_t)l*DD + tid];
    out[b*DD + tid] = acc;
}

// ---------------- launcher ----------------
extern "C" void kernel_launch(void* const* d_in, const int* in_sizes, int n_in,
                              void* d_out, int out_size)
{
    const float* gene   = (const float*)d_in[0];
    const float* coords = (const float*)d_in[1];
    const float* w_in   = (const float*)d_in[2];
    const float* b_in   = (const float*)d_in[3];
    const float* w_cls  = (const float*)d_in[4];
    const float* b_cls  = (const float*)d_in[5];
    const float* qkv_w  = (const float*)d_in[6];
    const float* qkv_b  = (const float*)d_in[7];
    const float* ln1_g  = (const float*)d_in[8];
    const float* ln1_b  = (const float*)d_in[9];
    const float* ffn_w1 = (const float*)d_in[10];
    const float* ffn_b1 = (const float*)d_in[11];
    const float* ffn_w2 = (const float*)d_in[12];
    const float* ffn_b2 = (const float*)d_in[13];
    const float* ln2_g  = (const float*)d_in[14];
    const float* ln2_b  = (const float*)d_in[15];
    const float* th1_w  = (const float*)d_in[16];
    const float* th1_b  = (const float*)d_in[17];
    const float* bn_g   = (const float*)d_in[18];
    const float* bn_b   = (const float*)d_in[19];
    const float* th2_w  = (const float*)d_in[20];
    const float* th2_b  = (const float*)d_in[21];
    float* out = (float*)d_out;

    const int gemm_smem = 2*GSTG*4;   // 61440 B
    cudaFuncSetAttribute(k_gemm_mma, cudaFuncAttributeMaxDynamicSharedMemorySize,
                         gemm_smem);

    k_wsplit<<<dim3(768/32, 256/32, NLAYER), 256>>>(qkv_w,  256, 768,  OFF_QKV);
    k_wsplit<<<dim3(1024/32, 256/32, NLAYER), 256>>>(ffn_w1, 256, 1024, OFF_FF1);
    k_wsplit<<<dim3(256/32, 1024/32, NLAYER), 256>>>(ffn_w2, 1024, 256, OFF_FF2);

    k_input<<<BB*LL, 256>>>(gene, coords, w_in, b_in, w_cls, b_cls);

    for (int l = 0; l < NLAYER; l++) {
        size_t wbase = (size_t)l*WSTRIDE;
        k_gemm_mma<<<dim3(768/64, MMP/128), 256, gemm_smem>>>(
            0, wbase + OFF_QKV, qkv_b + (size_t)l*768, 768, 256);
        k_attn<<<dim3(4, BB*HH), 256>>>();
        k_addln<<<MM/8, 256>>>(ln1_g + (size_t)l*DD, ln1_b + (size_t)l*DD, 1);
        k_gemm_mma<<<dim3(1024/64, MMP/128), 256, gemm_smem>>>(
            1, wbase + OFF_FF1, ffn_b1 + (size_t)l*FFD, 1024, 256);
        k_gemm_mma<<<dim3(256/64, MMP/128), 256, gemm_smem>>>(
            2, wbase + OFF_FF2, ffn_b2 + (size_t)l*DD, 256, 1024);
        k_addln<<<MM/8, 256>>>(ln2_g + (size_t)l*DD, ln2_b + (size_t)l*DD, (l < 3) ? 1 : 0);
    }

    k_head<<<(MM + 7)/8, 256>>>(th1_w, th1_b, bn_g, bn_b, th2_w, th2_b);
    k_pool<<<BB, 256>>>(out);
}

// round 13
// speedup vs baseline: 1.7010x; 1.3733x over previous
#include <cuda_runtime.h>
#include <cuda_fp16.h>
#include <math.h>
#include <stdint.h>

#define BB 64
#define TOK 64
#define NTK 456
#define LL 457
#define DD 256
#define HH 8
#define HD 32
#define NLAYER 4
#define FFD 1024
#define MM (BB*LL)          // 29248
#define MMP 29312           // padded to multiple of 128

#define WSTRIDE 720896      // per-layer elems in split weight buffer
#define OFF_QKV 0
#define OFF_FF1 196608
#define OFF_FF2 458752

// ---------------- device scratch ----------------
__device__ float g_x   [(size_t)MMP*DD];
__device__ float g_tmp [(size_t)MMP*DD];
__device__ float g_hsc [MM];
// fp16 activations (single plane) + K/V and weights (dual plane)
__device__ __half g_x1 [(size_t)MMP*DD];
__device__ __half g_f1 [(size_t)MMP*FFD];
__device__ __half g_q1 [(size_t)MMP*DD];
__device__ __half g_kvh[(size_t)MMP*512], g_kvl[(size_t)MMP*512];
__device__ __half g_wh[(size_t)NLAYER*WSTRIDE], g_wl[(size_t)NLAYER*WSTRIDE];

// ---------------- helpers ----------------
__device__ __forceinline__ uint32_t smem_u32(const void* p) {
    uint32_t a;
    asm("{ .reg .u64 t; cvta.to.shared.u64 t, %1; cvt.u32.u64 %0, t; }"
        : "=r"(a) : "l"(p));
    return a;
}
__device__ __forceinline__ uint32_t packh2(float a, float b) {
    __half2 h = __floats2half2_rn(a, b);
    return *reinterpret_cast<uint32_t*>(&h);
}

#define MMAF16(d, a0,a1,a2,a3, b0,b1) \
  asm volatile("mma.sync.aligned.m16n8k16.row.col.f32.f16.f16.f32 " \
    "{%0,%1,%2,%3}, {%4,%5,%6,%7}, {%8,%9}, {%0,%1,%2,%3};\n" \
    : "+f"(d[0]), "+f"(d[1]), "+f"(d[2]), "+f"(d[3]) \
    : "r"(a0), "r"(a1), "r"(a2), "r"(a3), "r"(b0), "r"(b1))

#define CP_ASYNC16(dst, src) \
  asm volatile("cp.async.cg.shared.global [%0], [%1], 16;\n" \
    :: "r"(dst), "l"(src) : "memory")
#define CP_COMMIT  asm volatile("cp.async.commit_group;\n" ::: "memory")
#define CP_WAIT1   asm volatile("cp.async.wait_group 1;\n" ::: "memory")

#define LDMX4(r0,r1,r2,r3, addr) \
  asm volatile("ldmatrix.sync.aligned.m8n8.x4.shared.b16 {%0,%1,%2,%3}, [%4];" \
    : "=r"(r0),"=r"(r1),"=r"(r2),"=r"(r3) : "r"(addr))
#define LDMX2(r0,r1, addr) \
  asm volatile("ldmatrix.sync.aligned.m8n8.x2.shared.b16 {%0,%1}, [%2];" \
    : "=r"(r0),"=r"(r1) : "r"(addr))
#define LDMX2T(r0,r1, addr) \
  asm volatile("ldmatrix.sync.aligned.m8n8.x2.trans.shared.b16 {%0,%1}, [%2];" \
    : "=r"(r0),"=r"(r1) : "r"(addr))

// ---------------- weight split + transpose: W[K][N] -> Wt planes [N][K] ----------------
__global__ __launch_bounds__(256) void k_wsplit(
    const float* __restrict__ W, int K, int N, size_t out_base)
{
    __shared__ float t[32][33];
    int l = blockIdx.z;
    const float* Wp = W + (size_t)l*K*N;
    int n0 = blockIdx.x*32, k0 = blockIdx.y*32;
    int tx = threadIdx.x & 31, ty = threadIdx.x >> 5;
    #pragma unroll
    for (int i = ty; i < 32; i += 8)
        t[i][tx] = Wp[(size_t)(k0+i)*N + n0 + tx];
    __syncthreads();
    #pragma unroll
    for (int i = ty; i < 32; i += 8) {
        float v = t[tx][i];   // = W[k0+tx][n0+i]
        size_t o = out_base + (size_t)l*WSTRIDE + (size_t)(n0+i)*K + (k0+tx);
        __half h = __float2half(v);
        g_wh[o] = h;
        g_wl[o] = __float2half(v - __half2float(h));
    }
}

// ---------------- input projection + CLS, 4 rows/block ----------------
__global__ __launch_bounds__(256) void k_input(
    const float* __restrict__ gene, const float* __restrict__ coords,
    const float* __restrict__ w_in, const float* __restrict__ b_in,
    const float* __restrict__ w_cls, const float* __restrict__ b_cls)
{
    __shared__ float sg[4][64];
    int tid = threadIdx.x;
    int row0 = blockIdx.x * 4;
    {
        int r = tid >> 6, cc = tid & 63;
        int row = row0 + r;
        int b = row / LL, l = row % LL;
        sg[r][cc] = (l > 0)
            ? gene[(size_t)b*(NTK*TOK) + (size_t)(l-1)*TOK + cc] : 0.f;
    }
    __syncthreads();
    int d = tid;
    float bi = b_in[d];
    float acc[4] = {bi, bi, bi, bi};
    #pragma unroll 8
    for (int k = 0; k < TOK; k++) {
        float wv = w_in[k*DD + d];
        #pragma unroll
        for (int r = 0; r < 4; r++) acc[r] += sg[r][k] * wv;
    }
    #pragma unroll
    for (int r = 0; r < 4; r++) {
        int row = row0 + r;
        int b = row / LL, l = row % LL;
        float v = acc[r];
        if (l == 0) {
            v = b_cls[d] + coords[b*3+0]*w_cls[d]
                         + coords[b*3+1]*w_cls[DD+d]
                         + coords[b*3+2]*w_cls[2*DD+d];
        }
        size_t off = (size_t)row*DD + d;
        g_x[off]  = v;
        g_x1[off] = __float2half(v);
    }
}

// ---------------- fp16 2-pass tensor-core GEMM, cp.async double-buffered ----------------
// C[M,N] = A[M,K] @ (Wh + Wl)[K,N] + bias. Block tile 128x64, warp tile 32x32, KB=32.
// sel 0: A=g_x1, C -> g_q1 (cols<256) / g_kvh+g_kvl (cols>=256)   (N=768, K=256)
// sel 1: A=g_x1, C -> relu -> g_f1                                 (N=1024, K=256)
// sel 2: A=g_f1, C -> g_tmp fp32                                   (N=256, K=1024)
// smem stage (words): A@0 (2560), BH@2560 (1280), BL@3840 (1280); stride 5120
#define GSTG 5120
__global__ __launch_bounds__(256) void k_gemm_mma(
    int sel, size_t woff, const float* __restrict__ bias, int N, int K)
{
    extern __shared__ __align__(16) uint32_t sm[];

    const __half* A1 = (sel == 2) ? g_f1 : g_x1;

    int tid = threadIdx.x;
    int wid = tid >> 5, lane = tid & 31;
    int g = lane >> 2, c = lane & 3;
    int wm = wid & 3, wn = wid >> 2;
    int bm = blockIdx.y * 128, bn = blockIdx.x * 64;
    uint32_t sbase = smem_u32(sm);

    float acc[2][4][4] = {};
    const int nch = K >> 5;

    auto issue_loads = [&](int ch, int st) {
        int k0 = ch << 5;
        uint32_t sb = sbase + (uint32_t)st*GSTG*4;
        #pragma unroll
        for (int e = 0; e < 2; e++) {
            int idx = tid + e*256;
            int m = idx >> 2, q = idx & 3;
            uint32_t d = sb + (uint32_t)(m*20 + q*4)*4;
            size_t go = (size_t)(bm + m)*K + k0 + q*8;
            CP_ASYNC16(d, (const char*)(A1 + go));
        }
        {
            int n = tid >> 2, q = tid & 3;
            uint32_t d = sb + (uint32_t)(2560 + n*20 + q*4)*4;
            size_t go = woff + (size_t)(bn + n)*K + k0 + q*8;
            CP_ASYNC16(d,          (const char*)(g_wh + go));
            CP_ASYNC16(d + 1280*4, (const char*)(g_wl + go));
        }
    };

    issue_loads(0, 0);
    CP_COMMIT;

    int lr = lane & 7, seg = lane >> 3;
    int l16 = lane & 15;

    for (int ch = 0; ch < nch; ch++) {
        if (ch + 1 < nch) issue_loads(ch + 1, (ch + 1) & 1);
        CP_COMMIT;
        CP_WAIT1;
        __syncthreads();

        uint32_t sb = sbase + (uint32_t)(ch & 1)*GSTG*4;
        uint32_t aH = sb, bH = sb + 2560*4, bL = sb + 3840*4;

        #pragma unroll
        for (int ks = 0; ks < 2; ks++) {
            uint32_t ah[2][4], bh[4][2], bl[4][2];
            #pragma unroll
            for (int mt = 0; mt < 2; mt++) {
                int row = wm*32 + mt*16 + lr + (seg & 1)*8;
                uint32_t ad = (uint32_t)(row*80 + ks*32 + (seg >> 1)*16);
                LDMX4(ah[mt][0], ah[mt][1], ah[mt][2], ah[mt][3], aH + ad);
            }
            #pragma unroll
            for (int nt = 0; nt < 4; nt++) {
                int row = wn*32 + nt*8 + (l16 & 7);
                uint32_t bd = (uint32_t)(row*80 + ks*32 + (l16 >> 3)*16);
                LDMX2(bh[nt][0], bh[nt][1], bH + bd);
                LDMX2(bl[nt][0], bl[nt][1], bL + bd);
            }
            #pragma unroll
            for (int mt = 0; mt < 2; mt++)
                #pragma unroll
                for (int nt = 0; nt < 4; nt++) {
                    MMAF16(acc[mt][nt], ah[mt][0],ah[mt][1],ah[mt][2],ah[mt][3],
                           bh[nt][0], bh[nt][1]);
                    MMAF16(acc[mt][nt], ah[mt][0],ah[mt][1],ah[mt][2],ah[mt][3],
                           bl[nt][0], bl[nt][1]);
                }
        }
        __syncthreads();
    }

    #pragma unroll
    for (int mt = 0; mt < 2; mt++) {
        int r0 = bm + wm*32 + mt*16 + g;
        #pragma unroll
        for (int nt = 0; nt < 4; nt++) {
            int cb = bn + wn*32 + nt*8 + 2*c;
            float2 bv = *reinterpret_cast<const float2*>(&bias[cb]);
            float v00 = acc[mt][nt][0] + bv.x, v01 = acc[mt][nt][1] + bv.y;
            float v10 = acc[mt][nt][2] + bv.x, v11 = acc[mt][nt][3] + bv.y;
            #pragma unroll
            for (int rr = 0; rr < 2; rr++) {
                size_t r = (size_t)(r0 + rr*8);
                float a = rr ? v10 : v00;
                float b2 = rr ? v11 : v01;
                if (sel == 2) {
                    *reinterpret_cast<float2*>(g_tmp + r*DD + cb) =
                        make_float2(a, b2);
                } else if (sel == 1) {
                    a = fmaxf(a, 0.f); b2 = fmaxf(b2, 0.f);
                    __half2 h = __floats2half2_rn(a, b2);
                    *reinterpret_cast<__half2*>(g_f1 + r*FFD + cb) = h;
                } else {
                    if (cb < 256) {
                        __half2 h = __floats2half2_rn(a, b2);
                        *reinterpret_cast<__half2*>(g_q1 + r*DD + cb) = h;
                    } else {
                        __half2 hi = __floats2half2_rn(a, b2);
                        __half2 lo = __floats2half2_rn(
                            a  - __half2float(hi.x),
                            b2 - __half2float(hi.y));
                        *reinterpret_cast<__half2*>(g_kvh + r*512 + cb - 256) = hi;
                        *reinterpret_cast<__half2*>(g_kvl + r*512 + cb - 256) = lo;
                    }
                }
            }
        }
    }
}

// ---------------- flash attention, fp16 2-pass mma, cp.async double-buffered ----------------
// block = 128 q-rows x (b,h). 8 warps, each 16 q-rows. j chunk = 64. 8 chunks.
__global__ __launch_bounds__(256) void k_attn()
{
    // per stage: KH,KL each 64x20 words; VH,VL same
    __shared__ uint32_t Ks[2][2][64*20];
    __shared__ uint32_t Vs[2][2][64*20];

    int gz = blockIdx.y;
    int b = gz >> 3, h = gz & 7;
    int qi0 = blockIdx.x * 128;
    int tid = threadIdx.x;
    int wq = tid >> 5, lane = tid & 31;
    int g = lane >> 2, c = lane & 3;
    int l16 = lane & 15;

    const float slope = (h < 4) ? 1.0f : 0.5f;
    const float scale = 0.17677669529663689f;   // 1/sqrt(32)

    // Q fragments (rows qi0+wq*16+g / +8), single plane
    uint32_t qh[2][4];
    {
        size_t r0 = ((size_t)b*LL + qi0 + wq*16 + g)*DD + h*HD;
        const __half* ph = g_q1 + r0;
        #pragma unroll
        for (int kt = 0; kt < 2; kt++) {
            qh[kt][0] = *(const uint32_t*)(ph + 16*kt + 2*c);
            qh[kt][1] = *(const uint32_t*)(ph + 8*DD + 16*kt + 2*c);
            qh[kt][2] = *(const uint32_t*)(ph + 16*kt + 2*c + 8);
            qh[kt][3] = *(const uint32_t*)(ph + 8*DD + 16*kt + 2*c + 8);
        }
    }

    int ldj = tid >> 2, ldq = tid & 3;
    auto issue_loads = [&](int ch, int st) {
        int j0 = ch << 6;
        size_t krow = ((size_t)b*LL + j0 + ldj)*512 + h*HD + ldq*8;
        uint32_t dk = smem_u32(&Ks[st][0][0]) + (uint32_t)(ldj*20 + ldq*4)*4;
        uint32_t dv = smem_u32(&Vs[st][0][0]) + (uint32_t)(ldj*20 + ldq*4)*4;
        CP_ASYNC16(dk,        (const char*)(g_kvh + krow));
        CP_ASYNC16(dk + 5120, (const char*)(g_kvl + krow));
        CP_ASYNC16(dv,        (const char*)(g_kvh + krow + 256));
        CP_ASYNC16(dv + 5120, (const char*)(g_kvl + krow + 256));
    };

    float oacc[4][4] = {};
    float m_run[2] = {-1e30f, -1e30f};
    float s_run[2] = {0.f, 0.f};

    issue_loads(0, 0);
    CP_COMMIT;

    const int nch = 8;
    for (int ch = 0; ch < nch; ch++) {
        if (ch + 1 < nch) issue_loads(ch + 1, (ch + 1) & 1);
        CP_COMMIT;
        CP_WAIT1;
        __syncthreads();

        int st = ch & 1;
        int j0 = ch << 6;
        uint32_t kH = smem_u32(&Ks[st][0][0]), kL = kH + 5120;
        uint32_t vH = smem_u32(&Vs[st][0][0]), vL = vH + 5120;

        // S = Q (Kh + Kl)^T
        float sacc[8][4] = {};
        #pragma unroll
        for (int nt = 0; nt < 8; nt++) {
            int row = nt*8 + (l16 & 7);
            #pragma unroll
            for (int kt = 0; kt < 2; kt++) {
                uint32_t bd = (uint32_t)(row*80 + kt*32 + (l16 >> 3)*16);
                uint32_t bh0, bh1, bl0, bl1;
                LDMX2(bh0, bh1, kH + bd);
                LDMX2(bl0, bl1, kL + bd);
                MMAF16(sacc[nt], qh[kt][0],qh[kt][1],qh[kt][2],qh[kt][3], bh0, bh1);
                MMAF16(sacc[nt], qh[kt][0],qh[kt][1],qh[kt][2],qh[kt][3], bl0, bl1);
            }
        }

        // online softmax on register fragments
        float corr[2];
        #pragma unroll
        for (int r = 0; r < 2; r++) {
            int qi = qi0 + wq*16 + g + r*8;
            float mloc = -1e30f;
            #pragma unroll
            for (int nt = 0; nt < 8; nt++) {
                #pragma unroll
                for (int e = 0; e < 2; e++) {
                    int kj = j0 + nt*8 + 2*c + e;
                    float v = sacc[nt][r*2+e]*scale - slope*fabsf((float)(qi - kj));
                    if (kj >= LL) v = -1e30f;
                    sacc[nt][r*2+e] = v;
                    mloc = fmaxf(mloc, v);
                }
            }
            mloc = fmaxf(mloc, __shfl_xor_sync(0xffffffffu, mloc, 1));
            mloc = fmaxf(mloc, __shfl_xor_sync(0xffffffffu, mloc, 2));
            float m_new = fmaxf(m_run[r], mloc);
            corr[r] = __expf(m_run[r] - m_new);
            float rs = 0.f;
            #pragma unroll
            for (int nt = 0; nt < 8; nt++) {
                #pragma unroll
                for (int e = 0; e < 2; e++) {
                    float p = __expf(sacc[nt][r*2+e] - m_new);
                    sacc[nt][r*2+e] = p;
                    rs += p;
                }
            }
            rs += __shfl_xor_sync(0xffffffffu, rs, 1);
            rs += __shfl_xor_sync(0xffffffffu, rs, 2);
            s_run[r] = s_run[r]*corr[r] + rs;
            m_run[r] = m_new;
        }
        #pragma unroll
        for (int nt = 0; nt < 4; nt++) {
            oacc[nt][0] *= corr[0]; oacc[nt][1] *= corr[0];
            oacc[nt][2] *= corr[1]; oacc[nt][3] *= corr[1];
        }

        // O += P (Vh + Vl)
        #pragma unroll
        for (int kt = 0; kt < 4; kt++) {
            uint32_t pa[4];
            pa[0] = packh2(sacc[2*kt][0],   sacc[2*kt][1]);
            pa[1] = packh2(sacc[2*kt][2],   sacc[2*kt][3]);
            pa[2] = packh2(sacc[2*kt+1][0], sacc[2*kt+1][1]);
            pa[3] = packh2(sacc[2*kt+1][2], sacc[2*kt+1][3]);
            int vrow = kt*16 + (l16 & 7) + (l16 >> 3)*8;
            #pragma unroll
            for (int nt = 0; nt < 4; nt++) {
                uint32_t bd = (uint32_t)(vrow*80 + nt*16);
                uint32_t bh0, bh1, bl0, bl1;
                LDMX2T(bh0, bh1, vH + bd);
                LDMX2T(bl0, bl1, vL + bd);
                MMAF16(oacc[nt], pa[0],pa[1],pa[2],pa[3], bh0, bh1);
                MMAF16(oacc[nt], pa[0],pa[1],pa[2],pa[3], bl0, bl1);
            }
        }
        __syncthreads();
    }

    float inv0 = 1.0f / s_run[0];
    float inv1 = 1.0f / s_run[1];
    int qi = qi0 + wq*16 + g;
    if (qi < LL) {
        float* o = g_tmp + ((size_t)b*LL + qi)*DD + h*HD;
        #pragma unroll
        for (int nt = 0; nt < 4; nt++)
            *reinterpret_cast<float2*>(o + nt*8 + 2*c) =
                make_float2(oacc[nt][0]*inv0, oacc[nt][1]*inv0);
    }
    if (qi + 8 < LL) {
        float* o = g_tmp + ((size_t)b*LL + qi + 8)*DD + h*HD;
        #pragma unroll
        for (int nt = 0; nt < 4; nt++)
            *reinterpret_cast<float2*>(o + nt*8 + 2*c) =
                make_float2(oacc[nt][2]*inv1, oacc[nt][3]*inv1);
    }
}

// ---------------- x = LN(x + tmp), warp-per-row, optional fp16 emit ----------------
__global__ __launch_bounds__(256) void k_addln(
    const float* __restrict__ gamma, const float* __restrict__ beta, int planes)
{
    int w = threadIdx.x >> 5, lane = threadIdx.x & 31;
    int row = blockIdx.x*8 + w;
    size_t base = (size_t)row*DD + lane*4;

    float4 a0 = *reinterpret_cast<const float4*>(&g_x[base]);
    float4 a1 = *reinterpret_cast<const float4*>(&g_x[base+128]);
    float4 t0 = *reinterpret_cast<const float4*>(&g_tmp[base]);
    float4 t1 = *reinterpret_cast<const float4*>(&g_tmp[base+128]);
    float v[8] = {a0.x+t0.x, a0.y+t0.y, a0.z+t0.z, a0.w+t0.w,
                  a1.x+t1.x, a1.y+t1.y, a1.z+t1.z, a1.w+t1.w};
    float s = 0.f, s2 = 0.f;
    #pragma unroll
    for (int i = 0; i < 8; i++) { s += v[i]; s2 += v[i]*v[i]; }
    #pragma unroll
    for (int off = 16; off > 0; off >>= 1) {
        s  += __shfl_xor_sync(0xffffffffu, s,  off);
        s2 += __shfl_xor_sync(0xffffffffu, s2, off);
    }
    float mean = s * (1.0f/256.0f);
    float var  = s2 * (1.0f/256.0f) - mean*mean;
    float inv  = rsqrtf(var + 1e-5f);

    float4 gg0 = *reinterpret_cast<const float4*>(&gamma[lane*4]);
    float4 gg1 = *reinterpret_cast<const float4*>(&gamma[128 + lane*4]);
    float4 bb0 = *reinterpret_cast<const float4*>(&beta[lane*4]);
    float4 bb1 = *reinterpret_cast<const float4*>(&beta[128 + lane*4]);
    float gv[8] = {gg0.x,gg0.y,gg0.z,gg0.w, gg1.x,gg1.y,gg1.z,gg1.w};
    float bv[8] = {bb0.x,bb0.y,bb0.z,bb0.w, bb1.x,bb1.y,bb1.z,bb1.w};
    float y[8];
    #pragma unroll
    for (int i = 0; i < 8; i++) y[i] = (v[i]-mean)*inv*gv[i] + bv[i];

    *reinterpret_cast<float4*>(&g_x[base])     = make_float4(y[0],y[1],y[2],y[3]);
    *reinterpret_cast<float4*>(&g_x[base+128]) = make_float4(y[4],y[5],y[6],y[7]);
    if (planes) {
        *reinterpret_cast<__half2*>(g_x1 + base)       = __floats2half2_rn(y[0], y[1]);
        *reinterpret_cast<__half2*>(g_x1 + base + 2)   = __floats2half2_rn(y[2], y[3]);
        *reinterpret_cast<__half2*>(g_x1 + base + 128) = __floats2half2_rn(y[4], y[5]);
        *reinterpret_cast<__half2*>(g_x1 + base + 130) = __floats2half2_rn(y[6], y[7]);
    }
}

// ---------------- head ----------------
__global__ __launch_bounds__(256) void k_head(
    const float* __restrict__ th1_w, const float* __restrict__ th1_b,
    const float* __restrict__ bn_g,  const float* __restrict__ bn_b,
    const float* __restrict__ th2_w, const float* __restrict__ th2_b)
{
    __shared__ float sx[8][256];
    __shared__ float sw1[256*32];
    int tid = threadIdx.x;
    int w = tid >> 5, lane = tid & 31;
    int row0 = blockIdx.x * 8;
    #pragma unroll
    for (int e = 0; e < 32; e++) sw1[tid + e*256] = th1_w[tid + e*256];
    #pragma unroll
    for (int e = 0; e < 8; e++) {
        int idx = tid + e*256;
        int r = idx >> 8, c = idx & 255;
        int row = row0 + r;
        sx[r][c] = (row < MM) ? g_x[(size_t)row*DD + c] : 0.f;
    }
    __syncthreads();
    int row = row0 + w;
    if (row < MM) {
        float acc = th1_b[lane];
        #pragma unroll 8
        for (int k = 0; k < 256; k++) acc += sx[w][k] * sw1[k*32 + lane];
        acc = acc * (bn_g[lane] * rsqrtf(1.0f + 1e-5f)) + bn_b[lane];
        float t = tanhf(0.7978845608028654f * (acc + 0.044715f*acc*acc*acc));
        float ge = 0.5f * acc * (1.0f + t);
        float ps = ge * th2_w[lane];
        #pragma unroll
        for (int s = 16; s > 0; s >>= 1) ps += __shfl_xor_sync(0xffffffffu, ps, s);
        if (lane == 0) g_hsc[row] = ps + th2_b[0];
    }
}

// ---------------- softmax over L + pooled output ----------------
__global__ __launch_bounds__(256) void k_pool(float* __restrict__ out)
{
    int b = blockIdx.x, tid = threadIdx.x;
    __shared__ float wv[LL];
    __shared__ float red[256];
    float v[2];
    #pragma unroll
    for (int i = 0; i < 2; i++) {
        int l = tid + i*256;
        v[i] = (l < LL) ? g_hsc[b*LL + l] : -1e30f;
    }
    float m = fmaxf(v[0], v[1]);
    red[tid] = m; __syncthreads();
    for (int s = 128; s > 0; s >>= 1) { if (tid < s) red[tid] = fmaxf(red[tid], red[tid+s]); __syncthreads(); }
    m = red[0]; __syncthreads();
    float sum = 0.f;
    #pragma unroll
    for (int i = 0; i < 2; i++) { v[i] = __expf(v[i] - m); sum += v[i]; }
    red[tid] = sum; __syncthreads();
    for (int s = 128; s > 0; s >>= 1) { if (tid < s) red[tid] += red[tid+s]; __syncthreads(); }
    float inv = 1.0f / red[0];
    #pragma unroll
    for (int i = 0; i < 2; i++) {
        int l = tid + i*256;
        if (l < LL) wv[l] = v[i] * inv;
    }
    __syncthreads();
    float acc = 0.f;
    const float* xb = g_x + (size_t)b*LL*DD;
    for (int l = 0; l < LL; l++) acc += wv[l] * xb[(size_t)l*DD + tid];
    out[b*DD + tid] = acc;
}

// ---------------- launcher ----------------
extern "C" void kernel_launch(void* const* d_in, const int* in_sizes, int n_in,
                              void* d_out, int out_size)
{
    const float* gene   = (const float*)d_in[0];
    const float* coords = (const float*)d_in[1];
    const float* w_in   = (const float*)d_in[2];
    const float* b_in   = (const float*)d_in[3];
    const float* w_cls  = (const float*)d_in[4];
    const float* b_cls  = (const float*)d_in[5];
    const float* qkv_w  = (const float*)d_in[6];
    const float* qkv_b  = (const float*)d_in[7];
    const float* ln1_g  = (const float*)d_in[8];
    const float* ln1_b  = (const float*)d_in[9];
    const float* ffn_w1 = (const float*)d_in[10];
    const float* ffn_b1 = (const float*)d_in[11];
    const float* ffn_w2 = (const float*)d_in[12];
    const float* ffn_b2 = (const float*)d_in[13];
    const float* ln2_g  = (const float*)d_in[14];
    const float* ln2_b  = (const float*)d_in[15];
    const float* th1_w  = (const float*)d_in[16];
    const float* th1_b  = (const float*)d_in[17];
    const float* bn_g   = (const float*)d_in[18];
    const float* bn_b   = (const float*)d_in[19];
    const float* th2_w  = (const float*)d_in[20];
    const float* th2_b  = (const float*)d_in[21];
    float* out = (float*)d_out;

    const int gemm_smem = 2*GSTG*4;   // 40960 B
    cudaFuncSetAttribute(k_gemm_mma, cudaFuncAttributeMaxDynamicSharedMemorySize,
                         gemm_smem);

    k_wsplit<<<dim3(768/32, 256/32, NLAYER), 256>>>(qkv_w,  256, 768,  OFF_QKV);
    k_wsplit<<<dim3(1024/32, 256/32, NLAYER), 256>>>(ffn_w1, 256, 1024, OFF_FF1);
    k_wsplit<<<dim3(256/32, 1024/32, NLAYER), 256>>>(ffn_w2, 1024, 256, OFF_FF2);

    k_input<<<MM/4, 256>>>(gene, coords, w_in, b_in, w_cls, b_cls);

    for (int l = 0; l < NLAYER; l++) {
        size_t wbase = (size_t)l*WSTRIDE;
        k_gemm_mma<<<dim3(768/64, MMP/128), 256, gemm_smem>>>(
            0, wbase + OFF_QKV, qkv_b + (size_t)l*768, 768, 256);
        k_attn<<<dim3(4, BB*HH), 256>>>();
        k_addln<<<MM/8, 256>>>(ln1_g + (size_t)l*DD, ln1_b + (size_t)l*DD, 1);
        k_gemm_mma<<<dim3(1024/64, MMP/128), 256, gemm_smem>>>(
            1, wbase + OFF_FF1, ffn_b1 + (size_t)l*FFD, 1024, 256);
        k_gemm_mma<<<dim3(256/64, MMP/128), 256, gemm_smem>>>(
            2, wbase + OFF_FF2, ffn_b2 + (size_t)l*DD, 256, 1024);
        k_addln<<<MM/8, 256>>>(ln2_g + (size_t)l*DD, ln2_b + (size_t)l*DD, (l < 3) ? 1 : 0);
    }

    k_head<<<(MM + 7)/8, 256>>>(th1_w, th1_b, bn_g, bn_b, th2_w, th2_b);
    k_pool<<<BB, 256>>>(out);
}

// round 15
// speedup vs baseline: 2.4364x; 1.4323x over previous
#include <cuda_runtime.h>
#include <cuda_fp16.h>
#include <math.h>
#include <stdint.h>

#define BB 64
#define TOK 64
#define NTK 456
#define LL 457
#define DD 256
#define HH 8
#define HD 32
#define NLAYER 4
#define FFD 1024
#define MM (BB*LL)          // 29248
#define MMP 29312           // padded to multiple of 128

#define WSTRIDE 720896      // per-layer elems in split weight buffer
#define OFF_QKV 0
#define OFF_FF1 196608
#define OFF_FF2 458752

// ---------------- device scratch ----------------
__device__ float g_x   [(size_t)MMP*DD];
__device__ float g_tmp [(size_t)MMP*DD];
__device__ float g_hsc [MM];
// fp16 single-plane activations / qkv / weights
__device__ __half g_x1 [(size_t)MMP*DD];
__device__ __half g_f1 [(size_t)MMP*FFD];
__device__ __half g_qv1[(size_t)MMP*768];
__device__ __half g_w1 [(size_t)NLAYER*WSTRIDE];

// ---------------- helpers ----------------
__device__ __forceinline__ uint32_t smem_u32(const void* p) {
    uint32_t a;
    asm("{ .reg .u64 t; cvta.to.shared.u64 t, %1; cvt.u32.u64 %0, t; }"
        : "=r"(a) : "l"(p));
    return a;
}
__device__ __forceinline__ uint32_t packh2(float a, float b) {
    __half2 h = __floats2half2_rn(a, b);
    return *reinterpret_cast<uint32_t*>(&h);
}

#define MMAF16(d, a0,a1,a2,a3, b0,b1) \
  asm volatile("mma.sync.aligned.m16n8k16.row.col.f32.f16.f16.f32 " \
    "{%0,%1,%2,%3}, {%4,%5,%6,%7}, {%8,%9}, {%0,%1,%2,%3};\n" \
    : "+f"(d[0]), "+f"(d[1]), "+f"(d[2]), "+f"(d[3]) \
    : "r"(a0), "r"(a1), "r"(a2), "r"(a3), "r"(b0), "r"(b1))

#define CP_ASYNC16(dst, src) \
  asm volatile("cp.async.cg.shared.global [%0], [%1], 16;\n" \
    :: "r"(dst), "l"(src) : "memory")
#define CP_COMMIT  asm volatile("cp.async.commit_group;\n" ::: "memory")
#define CP_WAIT1   asm volatile("cp.async.wait_group 1;\n" ::: "memory")

#define LDMX4(r0,r1,r2,r3, addr) \
  asm volatile("ldmatrix.sync.aligned.m8n8.x4.shared.b16 {%0,%1,%2,%3}, [%4];" \
    : "=r"(r0),"=r"(r1),"=r"(r2),"=r"(r3) : "r"(addr))
#define LDMX2(r0,r1, addr) \
  asm volatile("ldmatrix.sync.aligned.m8n8.x2.shared.b16 {%0,%1}, [%2];" \
    : "=r"(r0),"=r"(r1) : "r"(addr))
#define LDMX2T(r0,r1, addr) \
  asm volatile("ldmatrix.sync.aligned.m8n8.x2.trans.shared.b16 {%0,%1}, [%2];" \
    : "=r"(r0),"=r"(r1) : "r"(addr))

// ---------------- weight cast + transpose: W[K][N] -> Wt [N][K] fp16 ----------------
__global__ __launch_bounds__(256) void k_wsplit(
    const float* __restrict__ W, int K, int N, size_t out_base)
{
    __shared__ float t[32][33];
    int l = blockIdx.z;
    const float* Wp = W + (size_t)l*K*N;
    int n0 = blockIdx.x*32, k0 = blockIdx.y*32;
    int tx = threadIdx.x & 31, ty = threadIdx.x >> 5;
    #pragma unroll
    for (int i = ty; i < 32; i += 8)
        t[i][tx] = Wp[(size_t)(k0+i)*N + n0 + tx];
    __syncthreads();
    #pragma unroll
    for (int i = ty; i < 32; i += 8) {
        size_t o = out_base + (size_t)l*WSTRIDE + (size_t)(n0+i)*K + (k0+tx);
        g_w1[o] = __float2half(t[tx][i]);
    }
}

// ---------------- input projection + CLS, 4 rows/block ----------------
__global__ __launch_bounds__(256) void k_input(
    const float* __restrict__ gene, const float* __restrict__ coords,
    const float* __restrict__ w_in, const float* __restrict__ b_in,
    const float* __restrict__ w_cls, const float* __restrict__ b_cls)
{
    __shared__ float sg[4][64];
    int tid = threadIdx.x;
    int row0 = blockIdx.x * 4;
    {
        int r = tid >> 6, cc = tid & 63;
        int row = row0 + r;
        int b = row / LL, l = row % LL;
        sg[r][cc] = (l > 0)
            ? gene[(size_t)b*(NTK*TOK) + (size_t)(l-1)*TOK + cc] : 0.f;
    }
    __syncthreads();
    int d = tid;
    float bi = b_in[d];
    float acc[4] = {bi, bi, bi, bi};
    #pragma unroll 8
    for (int k = 0; k < TOK; k++) {
        float wv = w_in[k*DD + d];
        #pragma unroll
        for (int r = 0; r < 4; r++) acc[r] += sg[r][k] * wv;
    }
    #pragma unroll
    for (int r = 0; r < 4; r++) {
        int row = row0 + r;
        int b = row / LL, l = row % LL;
        float v = acc[r];
        if (l == 0) {
            v = b_cls[d] + coords[b*3+0]*w_cls[d]
                         + coords[b*3+1]*w_cls[DD+d]
                         + coords[b*3+2]*w_cls[2*DD+d];
        }
        size_t off = (size_t)row*DD + d;
        g_x[off]  = v;
        g_x1[off] = __float2half(v);
    }
}

// ---------------- fp16 single-pass tensor-core GEMM, cp.async double-buffered ----------------
// C[M,N] = A[M,K] @ W[K,N] + bias. Block tile 128x64, warp tile 32x32, KB=32.
// sel 0: A=g_x1, C -> g_qv1 fp16                 (N=768, K=256)
// sel 1: A=g_x1, C -> relu -> g_f1 fp16          (N=1024, K=256)
// sel 2: A=g_f1, C -> g_tmp fp32                 (N=256, K=1024)
// smem stage (words): A@0 (2560), B@2560 (1280); stride 3840
#define GSTG 3840
__global__ __launch_bounds__(256) void k_gemm_mma(
    int sel, size_t woff, const float* __restrict__ bias, int N, int K)
{
    extern __shared__ __align__(16) uint32_t sm[];

    const __half* A1 = (sel == 2) ? g_f1 : g_x1;

    int tid = threadIdx.x;
    int wid = tid >> 5, lane = tid & 31;
    int g = lane >> 2, c = lane & 3;
    int wm = wid & 3, wn = wid >> 2;
    int bm = blockIdx.y * 128, bn = blockIdx.x * 64;
    uint32_t sbase = smem_u32(sm);

    float acc[2][4][4] = {};
    const int nch = K >> 5;

    auto issue_loads = [&](int ch, int st) {
        int k0 = ch << 5;
        uint32_t sb = sbase + (uint32_t)st*GSTG*4;
        #pragma unroll
        for (int e = 0; e < 2; e++) {
            int idx = tid + e*256;
            int m = idx >> 2, q = idx & 3;
            uint32_t d = sb + (uint32_t)(m*20 + q*4)*4;
            size_t go = (size_t)(bm + m)*K + k0 + q*8;
            CP_ASYNC16(d, (const char*)(A1 + go));
        }
        {
            int n = tid >> 2, q = tid & 3;
            uint32_t d = sb + (uint32_t)(2560 + n*20 + q*4)*4;
            size_t go = woff + (size_t)(bn + n)*K + k0 + q*8;
            CP_ASYNC16(d, (const char*)(g_w1 + go));
        }
    };

    issue_loads(0, 0);
    CP_COMMIT;

    int lr = lane & 7, seg = lane >> 3;
    int l16 = lane & 15;

    for (int ch = 0; ch < nch; ch++) {
        if (ch + 1 < nch) issue_loads(ch + 1, (ch + 1) & 1);
        CP_COMMIT;
        CP_WAIT1;
        __syncthreads();

        uint32_t sb = sbase + (uint32_t)(ch & 1)*GSTG*4;
        uint32_t aH = sb, bH = sb + 2560*4;

        #pragma unroll
        for (int ks = 0; ks < 2; ks++) {
            uint32_t ah[2][4], bh[4][2];
            #pragma unroll
            for (int mt = 0; mt < 2; mt++) {
                int row = wm*32 + mt*16 + lr + (seg & 1)*8;
                uint32_t ad = (uint32_t)(row*80 + ks*32 + (seg >> 1)*16);
                LDMX4(ah[mt][0], ah[mt][1], ah[mt][2], ah[mt][3], aH + ad);
            }
            #pragma unroll
            for (int nt = 0; nt < 4; nt++) {
                int row = wn*32 + nt*8 + (l16 & 7);
                uint32_t bd = (uint32_t)(row*80 + ks*32 + (l16 >> 3)*16);
                LDMX2(bh[nt][0], bh[nt][1], bH + bd);
            }
            #pragma unroll
            for (int mt = 0; mt < 2; mt++)
                #pragma unroll
                for (int nt = 0; nt < 4; nt++)
                    MMAF16(acc[mt][nt], ah[mt][0],ah[mt][1],ah[mt][2],ah[mt][3],
                           bh[nt][0], bh[nt][1]);
        }
        __syncthreads();
    }

    #pragma unroll
    for (int mt = 0; mt < 2; mt++) {
        int r0 = bm + wm*32 + mt*16 + g;
        #pragma unroll
        for (int nt = 0; nt < 4; nt++) {
            int cb = bn + wn*32 + nt*8 + 2*c;
            float2 bv = *reinterpret_cast<const float2*>(&bias[cb]);
            float v00 = acc[mt][nt][0] + bv.x, v01 = acc[mt][nt][1] + bv.y;
            float v10 = acc[mt][nt][2] + bv.x, v11 = acc[mt][nt][3] + bv.y;
            #pragma unroll
            for (int rr = 0; rr < 2; rr++) {
                size_t r = (size_t)(r0 + rr*8);
                float a = rr ? v10 : v00;
                float b2 = rr ? v11 : v01;
                if (sel == 2) {
                    *reinterpret_cast<float2*>(g_tmp + r*DD + cb) =
                        make_float2(a, b2);
                } else if (sel == 1) {
                    a = fmaxf(a, 0.f); b2 = fmaxf(b2, 0.f);
                    *reinterpret_cast<__half2*>(g_f1 + r*FFD + cb) =
                        __floats2half2_rn(a, b2);
                } else {
                    *reinterpret_cast<__half2*>(g_qv1 + r*768 + cb) =
                        __floats2half2_rn(a, b2);
                }
            }
        }
    }
}

// ---------------- flash attention, fp16 single-pass mma, cp.async double-buffered ----------------
// block = 128 q-rows x (b,h). 8 warps, each 16 q-rows. j chunk = 64. 8 chunks.
__global__ __launch_bounds__(256) void k_attn()
{
    __shared__ uint32_t Ks[2][64*20];
    __shared__ uint32_t Vs[2][64*20];

    int gz = blockIdx.y;
    int b = gz >> 3, h = gz & 7;
    int qi0 = blockIdx.x * 128;
    int tid = threadIdx.x;
    int wq = tid >> 5, lane = tid & 31;
    int g = lane >> 2, c = lane & 3;
    int l16 = lane & 15;

    const float slope = (h < 4) ? 1.0f : 0.5f;
    const float scale = 0.17677669529663689f;   // 1/sqrt(32)

    // Q fragments (rows qi0+wq*16+g / +8)
    uint32_t qh[2][4];
    {
        size_t r0 = ((size_t)b*LL + qi0 + wq*16 + g)*768 + h*HD;
        const __half* ph = g_qv1 + r0;
        #pragma unroll
        for (int kt = 0; kt < 2; kt++) {
            qh[kt][0] = *(const uint32_t*)(ph + 16*kt + 2*c);
            qh[kt][1] = *(const uint32_t*)(ph + 8*768 + 16*kt + 2*c);
            qh[kt][2] = *(const uint32_t*)(ph + 16*kt + 2*c + 8);
            qh[kt][3] = *(const uint32_t*)(ph + 8*768 + 16*kt + 2*c + 8);
        }
    }

    int ldj = tid >> 2, ldq = tid & 3;
    auto issue_loads = [&](int ch, int st) {
        int j0 = ch << 6;
        size_t krow = ((size_t)b*LL + j0 + ldj)*768 + 256 + h*HD + ldq*8;
        uint32_t dk = smem_u32(&Ks[st][0]) + (uint32_t)(ldj*20 + ldq*4)*4;
        uint32_t dv = smem_u32(&Vs[st][0]) + (uint32_t)(ldj*20 + ldq*4)*4;
        CP_ASYNC16(dk, (const char*)(g_qv1 + krow));
        CP_ASYNC16(dv, (const char*)(g_qv1 + krow + 256));
    };

    float oacc[4][4] = {};
    float m_run[2] = {-1e30f, -1e30f};
    float s_run[2] = {0.f, 0.f};

    issue_loads(0, 0);
    CP_COMMIT;

    const int nch = 8;
    for (int ch = 0; ch < nch; ch++) {
        if (ch + 1 < nch) issue_loads(ch + 1, (ch + 1) & 1);
        CP_COMMIT;
        CP_WAIT1;
        __syncthreads();

        int st = ch & 1;
        int j0 = ch << 6;
        uint32_t kH = smem_u32(&Ks[st][0]);
        uint32_t vH = smem_u32(&Vs[st][0]);

        // S = Q K^T
        float sacc[8][4] = {};
        #pragma unroll
        for (int nt = 0; nt < 8; nt++) {
            int row = nt*8 + (l16 & 7);
            #pragma unroll
            for (int kt = 0; kt < 2; kt++) {
                uint32_t bd = (uint32_t)(row*80 + kt*32 + (l16 >> 3)*16);
                uint32_t bh0, bh1;
                LDMX2(bh0, bh1, kH + bd);
                MMAF16(sacc[nt], qh[kt][0],qh[kt][1],qh[kt][2],qh[kt][3], bh0, bh1);
            }
        }

        // online softmax on register fragments
        float corr[2];
        #pragma unroll
        for (int r = 0; r < 2; r++) {
            int qi = qi0 + wq*16 + g + r*8;
            float mloc = -1e30f;
            #pragma unroll
            for (int nt = 0; nt < 8; nt++) {
                #pragma unroll
                for (int e = 0; e < 2; e++) {
                    int kj = j0 + nt*8 + 2*c + e;
                    float v = sacc[nt][r*2+e]*scale - slope*fabsf((float)(qi - kj));
                    if (kj >= LL) v = -1e30f;
                    sacc[nt][r*2+e] = v;
                    mloc = fmaxf(mloc, v);
                }
            }
            mloc = fmaxf(mloc, __shfl_xor_sync(0xffffffffu, mloc, 1));
            mloc = fmaxf(mloc, __shfl_xor_sync(0xffffffffu, mloc, 2));
            float m_new = fmaxf(m_run[r], mloc);
            corr[r] = __expf(m_run[r] - m_new);
            float rs = 0.f;
            #pragma unroll
            for (int nt = 0; nt < 8; nt++) {
                #pragma unroll
                for (int e = 0; e < 2; e++) {
                    float p = __expf(sacc[nt][r*2+e] - m_new);
                    sacc[nt][r*2+e] = p;
                    rs += p;
                }
            }
            rs += __shfl_xor_sync(0xffffffffu, rs, 1);
            rs += __shfl_xor_sync(0xffffffffu, rs, 2);
            s_run[r] = s_run[r]*corr[r] + rs;
            m_run[r] = m_new;
        }
        #pragma unroll
        for (int nt = 0; nt < 4; nt++) {
            oacc[nt][0] *= corr[0]; oacc[nt][1] *= corr[0];
            oacc[nt][2] *= corr[1]; oacc[nt][3] *= corr[1];
        }

        // O += P V
        #pragma unroll
        for (int kt = 0; kt < 4; kt++) {
            uint32_t pa[4];
            pa[0] = packh2(sacc[2*kt][0],   sacc[2*kt][1]);
            pa[1] = packh2(sacc[2*kt][2],   sacc[2*kt][3]);
            pa[2] = packh2(sacc[2*kt+1][0], sacc[2*kt+1][1]);
            pa[3] = packh2(sacc[2*kt+1][2], sacc[2*kt+1][3]);
            int vrow = kt*16 + (l16 & 7) + (l16 >> 3)*8;
            #pragma unroll
            for (int nt = 0; nt < 4; nt++) {
                uint32_t bd = (uint32_t)(vrow*80 + nt*16);
                uint32_t bh0, bh1;
                LDMX2T(bh0, bh1, vH + bd);
                MMAF16(oacc[nt], pa[0],pa[1],pa[2],pa[3], bh0, bh1);
            }
        }
        __syncthreads();
    }

    float inv0 = 1.0f / s_run[0];
    float inv1 = 1.0f / s_run[1];
    int qi = qi0 + wq*16 + g;
    if (qi < LL) {
        float* o = g_tmp + ((size_t)b*LL + qi)*DD + h*HD;
        #pragma unroll
        for (int nt = 0; nt < 4; nt++)
            *reinterpret_cast<float2*>(o + nt*8 + 2*c) =
                make_float2(oacc[nt][0]*inv0, oacc[nt][1]*inv0);
    }
    if (qi + 8 < LL) {
        float* o = g_tmp + ((size_t)b*LL + qi + 8)*DD + h*HD;
        #pragma unroll
        for (int nt = 0; nt < 4; nt++)
            *reinterpret_cast<float2*>(o + nt*8 + 2*c) =
                make_float2(oacc[nt][2]*inv1, oacc[nt][3]*inv1);
    }
}

// ---------------- x = LN(x + tmp), warp-per-row, optional fp16 emit ----------------
__global__ __launch_bounds__(256) void k_addln(
    const float* __restrict__ gamma, const float* __restrict__ beta, int planes)
{
    int w = threadIdx.x >> 5, lane = threadIdx.x & 31;
    int row = blockIdx.x*8 + w;
    size_t base = (size_t)row*DD + lane*4;

    float4 a0 = *reinterpret_cast<const float4*>(&g_x[base]);
    float4 a1 = *reinterpret_cast<const float4*>(&g_x[base+128]);
    float4 t0 = *reinterpret_cast<const float4*>(&g_tmp[base]);
    float4 t1 = *reinterpret_cast<const float4*>(&g_tmp[base+128]);
    float v[8] = {a0.x+t0.x, a0.y+t0.y, a0.z+t0.z, a0.w+t0.w,
                  a1.x+t1.x, a1.y+t1.y, a1.z+t1.z, a1.w+t1.w};
    float s = 0.f, s2 = 0.f;
    #pragma unroll
    for (int i = 0; i < 8; i++) { s += v[i]; s2 += v[i]*v[i]; }
    #pragma unroll
    for (int off = 16; off > 0; off >>= 1) {
        s  += __shfl_xor_sync(0xffffffffu, s,  off);
        s2 += __shfl_xor_sync(0xffffffffu, s2, off);
    }
    float mean = s * (1.0f/256.0f);
    float var  = s2 * (1.0f/256.0f) - mean*mean;
    float inv  = rsqrtf(var + 1e-5f);

    float4 gg0 = *reinterpret_cast<const float4*>(&gamma[lane*4]);
    float4 gg1 = *reinterpret_cast<const float4*>(&gamma[128 + lane*4]);
    float4 bb0 = *reinterpret_cast<const float4*>(&beta[lane*4]);
    float4 bb1 = *reinterpret_cast<const float4*>(&beta[128 + lane*4]);
    float gv[8] = {gg0.x,gg0.y,gg0.z,gg0.w, gg1.x,gg1.y,gg1.z,gg1.w};
    float bv[8] = {bb0.x,bb0.y,bb0.z,bb0.w, bb1.x,bb1.y,bb1.z,bb1.w};
    float y[8];
    #pragma unroll
    for (int i = 0; i < 8; i++) y[i] = (v[i]-mean)*inv*gv[i] + bv[i];

    *reinterpret_cast<float4*>(&g_x[base])     = make_float4(y[0],y[1],y[2],y[3]);
    *reinterpret_cast<float4*>(&g_x[base+128]) = make_float4(y[4],y[5],y[6],y[7]);
    if (planes) {
        *reinterpret_cast<__half2*>(g_x1 + base)       = __floats2half2_rn(y[0], y[1]);
        *reinterpret_cast<__half2*>(g_x1 + base + 2)   = __floats2half2_rn(y[2], y[3]);
        *reinterpret_cast<__half2*>(g_x1 + base + 128) = __floats2half2_rn(y[4], y[5]);
        *reinterpret_cast<__half2*>(g_x1 + base + 130) = __floats2half2_rn(y[6], y[7]);
    }
}

// ---------------- head ----------------
__global__ __launch_bounds__(256) void k_head(
    const float* __restrict__ th1_w, const float* __restrict__ th1_b,
    const float* __restrict__ bn_g,  const float* __restrict__ bn_b,
    const float* __restrict__ th2_w, const float* __restrict__ th2_b)
{
    __shared__ float sx[8][256];
    __shared__ float sw1[256*32];
    int tid = threadIdx.x;
    int w = tid >> 5, lane = tid & 31;
    int row0 = blockIdx.x * 8;
    #pragma unroll
    for (int e = 0; e < 32; e++) sw1[tid + e*256] = th1_w[tid + e*256];
    #pragma unroll
    for (int e = 0; e < 8; e++) {
        int idx = tid + e*256;
        int r = idx >> 8, c = idx & 255;
        int row = row0 + r;
        sx[r][c] = (row < MM) ? g_x[(size_t)row*DD + c] : 0.f;
    }
    __syncthreads();
    int row = row0 + w;
    if (row < MM) {
        float acc = th1_b[lane];
        #pragma unroll 8
        for (int k = 0; k < 256; k++) acc += sx[w][k] * sw1[k*32 + lane];
        acc = acc * (bn_g[lane] * rsqrtf(1.0f + 1e-5f)) + bn_b[lane];
        float t = tanhf(0.7978845608028654f * (acc + 0.044715f*acc*acc*acc));
        float ge = 0.5f * acc * (1.0f + t);
        float ps = ge * th2_w[lane];
        #pragma unroll
        for (int s = 16; s > 0; s >>= 1) ps += __shfl_xor_sync(0xffffffffu, ps, s);
        if (lane == 0) g_hsc[row] = ps + th2_b[0];
    }
}

// ---------------- softmax over L + pooled output ----------------
__global__ __launch_bounds__(256) void k_pool(float* __restrict__ out)
{
    int b = blockIdx.x, tid = threadIdx.x;
    __shared__ float wv[LL];
    __shared__ float red[256];
    float v[2];
    #pragma unroll
    for (int i = 0; i < 2; i++) {
        int l = tid + i*256;
        v[i] = (l < LL) ? g_hsc[b*LL + l] : -1e30f;
    }
    float m = fmaxf(v[0], v[1]);
    red[tid] = m; __syncthreads();
    for (int s = 128; s > 0; s >>= 1) { if (tid < s) red[tid] = fmaxf(red[tid], red[tid+s]); __syncthreads(); }
    m = red[0]; __syncthreads();
    float sum = 0.f;
    #pragma unroll
    for (int i = 0; i < 2; i++) { v[i] = __expf(v[i] - m); sum += v[i]; }
    red[tid] = sum; __syncthreads();
    for (int s = 128; s > 0; s >>= 1) { if (tid < s) red[tid] += red[tid+s]; __syncthreads(); }
    float inv = 1.0f / red[0];
    #pragma unroll
    for (int i = 0; i < 2; i++) {
        int l = tid + i*256;
        if (l < LL) wv[l] = v[i] * inv;
    }
    __syncthreads();
    float acc = 0.f;
    const float* xb = g_x + (size_t)b*LL*DD;
    for (int l = 0; l < LL; l++) acc += wv[l] * xb[(size_t)l*DD + tid];
    out[b*DD + tid] = acc;
}

// ---------------- launcher ----------------
extern "C" void kernel_launch(void* const* d_in, const int* in_sizes, int n_in,
                              void* d_out, int out_size)
{
    const float* gene   = (const float*)d_in[0];
    const float* coords = (const float*)d_in[1];
    const float* w_in   = (const float*)d_in[2];
    const float* b_in   = (const float*)d_in[3];
    const float* w_cls  = (const float*)d_in[4];
    const float* b_cls  = (const float*)d_in[5];
    const float* qkv_w  = (const float*)d_in[6];
    const float* qkv_b  = (const float*)d_in[7];
    const float* ln1_g  = (const float*)d_in[8];
    const float* ln1_b  = (const float*)d_in[9];
    const float* ffn_w1 = (const float*)d_in[10];
    const float* ffn_b1 = (const float*)d_in[11];
    const float* ffn_w2 = (const float*)d_in[12];
    const float* ffn_b2 = (const float*)d_in[13];
    const float* ln2_g  = (const float*)d_in[14];
    const float* ln2_b  = (const float*)d_in[15];
    const float* th1_w  = (const float*)d_in[16];
    const float* th1_b  = (const float*)d_in[17];
    const float* bn_g   = (const float*)d_in[18];
    const float* bn_b   = (const float*)d_in[19];
    const float* th2_w  = (const float*)d_in[20];
    const float* th2_b  = (const float*)d_in[21];
    float* out = (float*)d_out;

    const int gemm_smem = 2*GSTG*4;   // 30720 B
    cudaFuncSetAttribute(k_gemm_mma, cudaFuncAttributeMaxDynamicSharedMemorySize,
                         gemm_smem);

    k_wsplit<<<dim3(768/32, 256/32, NLAYER), 256>>>(qkv_w,  256, 768,  OFF_QKV);
    k_wsplit<<<dim3(1024/32, 256/32, NLAYER), 256>>>(ffn_w1, 256, 1024, OFF_FF1);
    k_wsplit<<<dim3(256/32, 1024/32, NLAYER), 256>>>(ffn_w2, 1024, 256, OFF_FF2);

    k_input<<<MM/4, 256>>>(gene, coords, w_in, b_in, w_cls, b_cls);

    for (int l = 0; l < NLAYER; l++) {
        size_t wbase = (size_t)l*WSTRIDE;
        k_gemm_mma<<<dim3(768/64, MMP/128), 256, gemm_smem>>>(
            0, wbase + OFF_QKV, qkv_b + (size_t)l*768, 768, 256);
        k_attn<<<dim3(4, BB*HH), 256>>>();
        k_addln<<<MM/8, 256>>>(ln1_g + (size_t)l*DD, ln1_b + (size_t)l*DD, 1);
        k_gemm_mma<<<dim3(1024/64, MMP/128), 256, gemm_smem>>>(
            1, wbase + OFF_FF1, ffn_b1 + (size_t)l*FFD, 1024, 256);
        k_gemm_mma<<<dim3(256/64, MMP/128), 256, gemm_smem>>>(
            2, wbase + OFF_FF2, ffn_b2 + (size_t)l*DD, 256, 1024);
        k_addln<<<MM/8, 256>>>(ln2_g + (size_t)l*DD, ln2_b + (size_t)l*DD, (l < 3) ? 1 : 0);
    }

    k_head<<<(MM + 7)/8, 256>>>(th1_w, th1_b, bn_g, bn_b, th2_w, th2_b);
    k_pool<<<BB, 256>>>(out);
}

// round 16
// speedup vs baseline: 2.6323x; 1.0804x over previous
#include <cuda_runtime.h>
#include <cuda_fp16.h>
#include <math.h>
#include <stdint.h>

#define BB 64
#define TOK 64
#define NTK 456
#define LL 457
#define DD 256
#define HH 8
#define HD 32
#define NLAYER 4
#define FFD 1024
#define MM (BB*LL)          // 29248
#define MMP 29312           // padded to multiple of 128

#define WSTRIDE 720896      // per-layer elems in split weight buffer
#define OFF_QKV 0
#define OFF_FF1 196608
#define OFF_FF2 458752

// ---------------- device scratch ----------------
__device__ float g_x   [(size_t)MMP*DD];
__device__ float g_tmp [(size_t)MMP*DD];
__device__ float g_hsc [MM];
// fp16 single-plane activations / qkv / weights
__device__ __half g_x1 [(size_t)MMP*DD];
__device__ __half g_f1 [(size_t)MMP*FFD];
__device__ __half g_qv1[(size_t)MMP*768];
__device__ __half g_w1 [(size_t)NLAYER*WSTRIDE];

// ---------------- helpers ----------------
__device__ __forceinline__ uint32_t smem_u32(const void* p) {
    uint32_t a;
    asm("{ .reg .u64 t; cvta.to.shared.u64 t, %1; cvt.u32.u64 %0, t; }"
        : "=r"(a) : "l"(p));
    return a;
}
__device__ __forceinline__ uint32_t packh2(float a, float b) {
    __half2 h = __floats2half2_rn(a, b);
    return *reinterpret_cast<uint32_t*>(&h);
}

#define MMAF16(d, a0,a1,a2,a3, b0,b1) \
  asm volatile("mma.sync.aligned.m16n8k16.row.col.f32.f16.f16.f32 " \
    "{%0,%1,%2,%3}, {%4,%5,%6,%7}, {%8,%9}, {%0,%1,%2,%3};\n" \
    : "+f"(d[0]), "+f"(d[1]), "+f"(d[2]), "+f"(d[3]) \
    : "r"(a0), "r"(a1), "r"(a2), "r"(a3), "r"(b0), "r"(b1))

#define CP_ASYNC16(dst, src) \
  asm volatile("cp.async.cg.shared.global [%0], [%1], 16;\n" \
    :: "r"(dst), "l"(src) : "memory")
#define CP_COMMIT  asm volatile("cp.async.commit_group;\n" ::: "memory")
#define CP_WAIT1   asm volatile("cp.async.wait_group 1;\n" ::: "memory")

#define LDMX4(r0,r1,r2,r3, addr) \
  asm volatile("ldmatrix.sync.aligned.m8n8.x4.shared.b16 {%0,%1,%2,%3}, [%4];" \
    : "=r"(r0),"=r"(r1),"=r"(r2),"=r"(r3) : "r"(addr))
#define LDMX4T(r0,r1,r2,r3, addr) \
  asm volatile("ldmatrix.sync.aligned.m8n8.x4.trans.shared.b16 {%0,%1,%2,%3}, [%4];" \
    : "=r"(r0),"=r"(r1),"=r"(r2),"=r"(r3) : "r"(addr))

// ---------------- weight cast + transpose: W[K][N] -> Wt [N][K] fp16 ----------------
__global__ __launch_bounds__(256) void k_wsplit(
    const float* __restrict__ W, int K, int N, size_t out_base)
{
    __shared__ float t[32][33];
    int l = blockIdx.z;
    const float* Wp = W + (size_t)l*K*N;
    int n0 = blockIdx.x*32, k0 = blockIdx.y*32;
    int tx = threadIdx.x & 31, ty = threadIdx.x >> 5;
    #pragma unroll
    for (int i = ty; i < 32; i += 8)
        t[i][tx] = Wp[(size_t)(k0+i)*N + n0 + tx];
    __syncthreads();
    #pragma unroll
    for (int i = ty; i < 32; i += 8) {
        size_t o = out_base + (size_t)l*WSTRIDE + (size_t)(n0+i)*K + (k0+tx);
        g_w1[o] = __float2half(t[tx][i]);
    }
}

// ---------------- input projection + CLS, 8 rows/block ----------------
__global__ __launch_bounds__(256) void k_input(
    const float* __restrict__ gene, const float* __restrict__ coords,
    const float* __restrict__ w_in, const float* __restrict__ b_in,
    const float* __restrict__ w_cls, const float* __restrict__ b_cls)
{
    __shared__ float sg[8][64];
    int tid = threadIdx.x;
    int row0 = blockIdx.x * 8;
    #pragma unroll
    for (int e = 0; e < 2; e++) {
        int idx = tid + e*256;
        int r = idx >> 6, cc = idx & 63;
        int row = row0 + r;
        int b = row / LL, l = row % LL;
        sg[r][cc] = (l > 0)
            ? gene[(size_t)b*(NTK*TOK) + (size_t)(l-1)*TOK + cc] : 0.f;
    }
    __syncthreads();
    int d = tid;
    float bi = b_in[d];
    float acc[8] = {bi, bi, bi, bi, bi, bi, bi, bi};
    #pragma unroll 8
    for (int k = 0; k < TOK; k++) {
        float wv = w_in[k*DD + d];
        #pragma unroll
        for (int r = 0; r < 8; r++) acc[r] += sg[r][k] * wv;
    }
    #pragma unroll
    for (int r = 0; r < 8; r++) {
        int row = row0 + r;
        int b = row / LL, l = row % LL;
        float v = acc[r];
        if (l == 0) {
            v = b_cls[d] + coords[b*3+0]*w_cls[d]
                         + coords[b*3+1]*w_cls[DD+d]
                         + coords[b*3+2]*w_cls[2*DD+d];
        }
        size_t off = (size_t)row*DD + d;
        g_x[off]  = v;
        g_x1[off] = __float2half(v);
    }
}

// ---------------- fp16 tensor-core GEMM: block 128x128, warp 32x64 ----------------
// C[M,N] = A[M,K] @ W[K,N] + bias.
// sel 0: A=g_x1, C -> g_qv1 fp16                 (N=768, K=256)
// sel 1: A=g_x1, C -> relu -> g_f1 fp16          (N=1024, K=256)
// sel 2: A=g_f1, C -> g_tmp fp32                 (N=256, K=1024)
// smem stage (words): A@0 (2560), B@2560 (2560); stride 5120
#define GSTG 5120
__global__ __launch_bounds__(256, 2) void k_gemm_mma(
    int sel, size_t woff, const float* __restrict__ bias, int N, int K)
{
    extern __shared__ __align__(16) uint32_t sm[];

    const __half* A1 = (sel == 2) ? g_f1 : g_x1;

    int tid = threadIdx.x;
    int wid = tid >> 5, lane = tid & 31;
    int g = lane >> 2, c = lane & 3;
    int wm = wid & 3, wn = wid >> 2;        // 4 x 2 warp grid
    int bm = blockIdx.y * 128, bn = blockIdx.x * 128;
    uint32_t sbase = smem_u32(sm);

    float acc[2][8][4] = {};
    const int nch = K >> 5;

    auto issue_loads = [&](int ch, int st) {
        int k0 = ch << 5;
        uint32_t sb = sbase + (uint32_t)st*GSTG*4;
        #pragma unroll
        for (int e = 0; e < 2; e++) {
            int idx = tid + e*256;
            int m = idx >> 2, q = idx & 3;
            uint32_t d = sb + (uint32_t)(m*20 + q*4)*4;
            size_t go = (size_t)(bm + m)*K + k0 + q*8;
            CP_ASYNC16(d, (const char*)(A1 + go));
        }
        #pragma unroll
        for (int e = 0; e < 2; e++) {
            int idx = tid + e*256;
            int n = idx >> 2, q = idx & 3;
            uint32_t d = sb + (uint32_t)(2560 + n*20 + q*4)*4;
            size_t go = woff + (size_t)(bn + n)*K + k0 + q*8;
            CP_ASYNC16(d, (const char*)(g_w1 + go));
        }
    };

    issue_loads(0, 0);
    CP_COMMIT;

    int lr = lane & 7, seg = lane >> 3;   // for A loads
    int grp = lane >> 3;                  // for B x4 loads

    for (int ch = 0; ch < nch; ch++) {
        if (ch + 1 < nch) issue_loads(ch + 1, (ch + 1) & 1);
        CP_COMMIT;
        CP_WAIT1;
        __syncthreads();

        uint32_t sb = sbase + (uint32_t)(ch & 1)*GSTG*4;
        uint32_t aH = sb, bH = sb + 2560*4;

        #pragma unroll
        for (int ks = 0; ks < 2; ks++) {
            uint32_t ah[2][4], bh[8][2];
            #pragma unroll
            for (int mt = 0; mt < 2; mt++) {
                int row = wm*32 + mt*16 + lr + (seg & 1)*8;
                uint32_t ad = (uint32_t)(row*80 + ks*32 + (seg >> 1)*16);
                LDMX4(ah[mt][0], ah[mt][1], ah[mt][2], ah[mt][3], aH + ad);
            }
            #pragma unroll
            for (int ntp = 0; ntp < 4; ntp++) {
                // x4: tiles (nt,k0),(nt,k1),(nt+1,k0),(nt+1,k1)
                int row = wn*64 + ntp*16 + (grp >> 1)*8 + lr;
                uint32_t bd = (uint32_t)(row*80 + ks*32 + (grp & 1)*16);
                LDMX4(bh[2*ntp][0], bh[2*ntp][1],
                      bh[2*ntp+1][0], bh[2*ntp+1][1], bH + bd);
            }
            #pragma unroll
            for (int mt = 0; mt < 2; mt++)
                #pragma unroll
                for (int nt = 0; nt < 8; nt++)
                    MMAF16(acc[mt][nt], ah[mt][0],ah[mt][1],ah[mt][2],ah[mt][3],
                           bh[nt][0], bh[nt][1]);
        }
        __syncthreads();
    }

    #pragma unroll
    for (int mt = 0; mt < 2; mt++) {
        int r0 = bm + wm*32 + mt*16 + g;
        #pragma unroll
        for (int nt = 0; nt < 8; nt++) {
            int cb = bn + wn*64 + nt*8 + 2*c;
            float2 bv = *reinterpret_cast<const float2*>(&bias[cb]);
            float v00 = acc[mt][nt][0] + bv.x, v01 = acc[mt][nt][1] + bv.y;
            float v10 = acc[mt][nt][2] + bv.x, v11 = acc[mt][nt][3] + bv.y;
            #pragma unroll
            for (int rr = 0; rr < 2; rr++) {
                size_t r = (size_t)(r0 + rr*8);
                float a = rr ? v10 : v00;
                float b2 = rr ? v11 : v01;
                if (sel == 2) {
                    *reinterpret_cast<float2*>(g_tmp + r*DD + cb) =
                        make_float2(a, b2);
                } else if (sel == 1) {
                    a = fmaxf(a, 0.f); b2 = fmaxf(b2, 0.f);
                    *reinterpret_cast<__half2*>(g_f1 + r*FFD + cb) =
                        __floats2half2_rn(a, b2);
                } else {
                    *reinterpret_cast<__half2*>(g_qv1 + r*768 + cb) =
                        __floats2half2_rn(a, b2);
                }
            }
        }
    }
}

// ---------------- flash attention, fp16 single-pass mma, cp.async double-buffered ----------------
// block = 128 q-rows x (b,h). 8 warps, each 16 q-rows. j chunk = 64. 8 chunks.
__global__ __launch_bounds__(256) void k_attn()
{
    __shared__ uint32_t Ks[2][64*20];
    __shared__ uint32_t Vs[2][64*20];

    int gz = blockIdx.y;
    int b = gz >> 3, h = gz & 7;
    int qi0 = blockIdx.x * 128;
    int tid = threadIdx.x;
    int wq = tid >> 5, lane = tid & 31;
    int g = lane >> 2, c = lane & 3;
    int lr = lane & 7, grp = lane >> 3;

    const float slope = (h < 4) ? 1.0f : 0.5f;
    const float scale = 0.17677669529663689f;   // 1/sqrt(32)

    // Q fragments (rows qi0+wq*16+g / +8)
    uint32_t qh[2][4];
    {
        size_t r0 = ((size_t)b*LL + qi0 + wq*16 + g)*768 + h*HD;
        const __half* ph = g_qv1 + r0;
        #pragma unroll
        for (int kt = 0; kt < 2; kt++) {
            qh[kt][0] = *(const uint32_t*)(ph + 16*kt + 2*c);
            qh[kt][1] = *(const uint32_t*)(ph + 8*768 + 16*kt + 2*c);
            qh[kt][2] = *(const uint32_t*)(ph + 16*kt + 2*c + 8);
            qh[kt][3] = *(const uint32_t*)(ph + 8*768 + 16*kt + 2*c + 8);
        }
    }

    int ldj = tid >> 2, ldq = tid & 3;
    auto issue_loads = [&](int ch, int st) {
        int j0 = ch << 6;
        size_t krow = ((size_t)b*LL + j0 + ldj)*768 + 256 + h*HD + ldq*8;
        uint32_t dk = smem_u32(&Ks[st][0]) + (uint32_t)(ldj*20 + ldq*4)*4;
        uint32_t dv = smem_u32(&Vs[st][0]) + (uint32_t)(ldj*20 + ldq*4)*4;
        CP_ASYNC16(dk, (const char*)(g_qv1 + krow));
        CP_ASYNC16(dv, (const char*)(g_qv1 + krow + 256));
    };

    float oacc[4][4] = {};
    float m_run[2] = {-1e30f, -1e30f};
    float s_run[2] = {0.f, 0.f};

    issue_loads(0, 0);
    CP_COMMIT;

    const int nch = 8;
    for (int ch = 0; ch < nch; ch++) {
        if (ch + 1 < nch) issue_loads(ch + 1, (ch + 1) & 1);
        CP_COMMIT;
        CP_WAIT1;
        __syncthreads();

        int st = ch & 1;
        int j0 = ch << 6;
        uint32_t kH = smem_u32(&Ks[st][0]);
        uint32_t vH = smem_u32(&Vs[st][0]);

        // S = Q K^T  (B frags via x4: two j-tiles per ldmatrix)
        float sacc[8][4] = {};
        #pragma unroll
        for (int kt = 0; kt < 2; kt++) {
            uint32_t bh[8][2];
            #pragma unroll
            for (int ntp = 0; ntp < 4; ntp++) {
                int row = ntp*16 + (grp >> 1)*8 + lr;
                uint32_t bd = (uint32_t)(row*80 + kt*32 + (grp & 1)*16);
                LDMX4(bh[2*ntp][0], bh[2*ntp][1],
                      bh[2*ntp+1][0], bh[2*ntp+1][1], kH + bd);
            }
            #pragma unroll
            for (int nt = 0; nt < 8; nt++)
                MMAF16(sacc[nt], qh[kt][0],qh[kt][1],qh[kt][2],qh[kt][3],
                       bh[nt][0], bh[nt][1]);
        }

        // online softmax on register fragments
        float corr[2];
        #pragma unroll
        for (int r = 0; r < 2; r++) {
            int qi = qi0 + wq*16 + g + r*8;
            float mloc = -1e30f;
            #pragma unroll
            for (int nt = 0; nt < 8; nt++) {
                #pragma unroll
                for (int e = 0; e < 2; e++) {
                    int kj = j0 + nt*8 + 2*c + e;
                    float v = sacc[nt][r*2+e]*scale - slope*fabsf((float)(qi - kj));
                    if (kj >= LL) v = -1e30f;
                    sacc[nt][r*2+e] = v;
                    mloc = fmaxf(mloc, v);
                }
            }
            mloc = fmaxf(mloc, __shfl_xor_sync(0xffffffffu, mloc, 1));
            mloc = fmaxf(mloc, __shfl_xor_sync(0xffffffffu, mloc, 2));
            float m_new = fmaxf(m_run[r], mloc);
            corr[r] = __expf(m_run[r] - m_new);
            float rs = 0.f;
            #pragma unroll
            for (int nt = 0; nt < 8; nt++) {
                #pragma unroll
                for (int e = 0; e < 2; e++) {
                    float p = __expf(sacc[nt][r*2+e] - m_new);
                    sacc[nt][r*2+e] = p;
                    rs += p;
                }
            }
            rs += __shfl_xor_sync(0xffffffffu, rs, 1);
            rs += __shfl_xor_sync(0xffffffffu, rs, 2);
            s_run[r] = s_run[r]*corr[r] + rs;
            m_run[r] = m_new;
        }
        #pragma unroll
        for (int nt = 0; nt < 4; nt++) {
            oacc[nt][0] *= corr[0]; oacc[nt][1] *= corr[0];
            oacc[nt][2] *= corr[1]; oacc[nt][3] *= corr[1];
        }

        // O += P V  (V frags via x4 trans: two d-tiles per ldmatrix)
        #pragma unroll
        for (int kt = 0; kt < 4; kt++) {
            uint32_t pa[4];
            pa[0] = packh2(sacc[2*kt][0],   sacc[2*kt][1]);
            pa[1] = packh2(sacc[2*kt][2],   sacc[2*kt][3]);
            pa[2] = packh2(sacc[2*kt+1][0], sacc[2*kt+1][1]);
            pa[3] = packh2(sacc[2*kt+1][2], sacc[2*kt+1][3]);
            #pragma unroll
            for (int ntp = 0; ntp < 2; ntp++) {
                // x4 trans: tiles (j0-7,d),(j8-15,d),(j0-7,d+8),(j8-15,d+8)
                int vrow = kt*16 + (grp & 1)*8 + lr;
                uint32_t bd = (uint32_t)(vrow*80 + (ntp*2 + (grp >> 1))*16);
                uint32_t b0, b1, b2, b3;
                LDMX4T(b0, b1, b2, b3, vH + bd);
                MMAF16(oacc[2*ntp],   pa[0],pa[1],pa[2],pa[3], b0, b1);
                MMAF16(oacc[2*ntp+1], pa[0],pa[1],pa[2],pa[3], b2, b3);
            }
        }
        __syncthreads();
    }

    float inv0 = 1.0f / s_run[0];
    float inv1 = 1.0f / s_run[1];
    int qi = qi0 + wq*16 + g;
    if (qi < LL) {
        float* o = g_tmp + ((size_t)b*LL + qi)*DD + h*HD;
        #pragma unroll
        for (int nt = 0; nt < 4; nt++)
            *reinterpret_cast<float2*>(o + nt*8 + 2*c) =
                make_float2(oacc[nt][0]*inv0, oacc[nt][1]*inv0);
    }
    if (qi + 8 < LL) {
        float* o = g_tmp + ((size_t)b*LL + qi + 8)*DD + h*HD;
        #pragma unroll
        for (int nt = 0; nt < 4; nt++)
            *reinterpret_cast<float2*>(o + nt*8 + 2*c) =
                make_float2(oacc[nt][2]*inv1, oacc[nt][3]*inv1);
    }
}

// ---------------- x = LN(x + tmp), warp-per-row, optional fp16 emit ----------------
__global__ __launch_bounds__(256) void k_addln(
    const float* __restrict__ gamma, const float* __restrict__ beta, int planes)
{
    int w = threadIdx.x >> 5, lane = threadIdx.x & 31;
    int row = blockIdx.x*8 + w;
    size_t base = (size_t)row*DD + lane*4;

    float4 a0 = *reinterpret_cast<const float4*>(&g_x[base]);
    float4 a1 = *reinterpret_cast<const float4*>(&g_x[base+128]);
    float4 t0 = *reinterpret_cast<const float4*>(&g_tmp[base]);
    float4 t1 = *reinterpret_cast<const float4*>(&g_tmp[base+128]);
    float v[8] = {a0.x+t0.x, a0.y+t0.y, a0.z+t0.z, a0.w+t0.w,
                  a1.x+t1.x, a1.y+t1.y, a1.z+t1.z, a1.w+t1.w};
    float s = 0.f, s2 = 0.f;
    #pragma unroll
    for (int i = 0; i < 8; i++) { s += v[i]; s2 += v[i]*v[i]; }
    #pragma unroll
    for (int off = 16; off > 0; off >>= 1) {
        s  += __shfl_xor_sync(0xffffffffu, s,  off);
        s2 += __shfl_xor_sync(0xffffffffu, s2, off);
    }
    float mean = s * (1.0f/256.0f);
    float var  = s2 * (1.0f/256.0f) - mean*mean;
    float inv  = rsqrtf(var + 1e-5f);

    float4 gg0 = *reinterpret_cast<const float4*>(&gamma[lane*4]);
    float4 gg1 = *reinterpret_cast<const float4*>(&gamma[128 + lane*4]);
    float4 bb0 = *reinterpret_cast<const float4*>(&beta[lane*4]);
    float4 bb1 = *reinterpret_cast<const float4*>(&beta[128 + lane*4]);
    float gv[8] = {gg0.x,gg0.y,gg0.z,gg0.w, gg1.x,gg1.y,gg1.z,gg1.w};
    float bv[8] = {bb0.x,bb0.y,bb0.z,bb0.w, bb1.x,bb1.y,bb1.z,bb1.w};
    float y[8];
    #pragma unroll
    for (int i = 0; i < 8; i++) y[i] = (v[i]-mean)*inv*gv[i] + bv[i];

    *reinterpret_cast<float4*>(&g_x[base])     = make_float4(y[0],y[1],y[2],y[3]);
    *reinterpret_cast<float4*>(&g_x[base+128]) = make_float4(y[4],y[5],y[6],y[7]);
    if (planes) {
        *reinterpret_cast<__half2*>(g_x1 + base)       = __floats2half2_rn(y[0], y[1]);
        *reinterpret_cast<__half2*>(g_x1 + base + 2)   = __floats2half2_rn(y[2], y[3]);
        *reinterpret_cast<__half2*>(g_x1 + base + 128) = __floats2half2_rn(y[4], y[5]);
        *reinterpret_cast<__half2*>(g_x1 + base + 130) = __floats2half2_rn(y[6], y[7]);
    }
}

// ---------------- head ----------------
__global__ __launch_bounds__(256) void k_head(
    const float* __restrict__ th1_w, const float* __restrict__ th1_b,
    const float* __restrict__ bn_g,  const float* __restrict__ bn_b,
    const float* __restrict__ th2_w, const float* __restrict__ th2_b)
{
    __shared__ float sx[8][256];
    __shared__ float sw1[256*32];
    int tid = threadIdx.x;
    int w = tid >> 5, lane = tid & 31;
    int row0 = blockIdx.x * 8;
    #pragma unroll
    for (int e = 0; e < 32; e++) sw1[tid + e*256] = th1_w[tid + e*256];
    #pragma unroll
    for (int e = 0; e < 8; e++) {
        int idx = tid + e*256;
        int r = idx >> 8, c = idx & 255;
        int row = row0 + r;
        sx[r][c] = (row < MM) ? g_x[(size_t)row*DD + c] : 0.f;
    }
    __syncthreads();
    int row = row0 + w;
    if (row < MM) {
        float acc = th1_b[lane];
        #pragma unroll 8
        for (int k = 0; k < 256; k++) acc += sx[w][k] * sw1[k*32 + lane];
        acc = acc * (bn_g[lane] * rsqrtf(1.0f + 1e-5f)) + bn_b[lane];
        float t = tanhf(0.7978845608028654f * (acc + 0.044715f*acc*acc*acc));
        float ge = 0.5f * acc * (1.0f + t);
        float ps = ge * th2_w[lane];
        #pragma unroll
        for (int s = 16; s > 0; s >>= 1) ps += __shfl_xor_sync(0xffffffffu, ps, s);
        if (lane == 0) g_hsc[row] = ps + th2_b[0];
    }
}

// ---------------- softmax over L + pooled output ----------------
__global__ __launch_bounds__(256) void k_pool(float* __restrict__ out)
{
    int b = blockIdx.x, tid = threadIdx.x;
    __shared__ float wv[LL];
    __shared__ float red[256];
    float v[2];
    #pragma unroll
    for (int i = 0; i < 2; i++) {
        int l = tid + i*256;
        v[i] = (l < LL) ? g_hsc[b*LL + l] : -1e30f;
    }
    float m = fmaxf(v[0], v[1]);
    red[tid] = m; __syncthreads();
    for (int s = 128; s > 0; s >>= 1) { if (tid < s) red[tid] = fmaxf(red[tid], red[tid+s]); __syncthreads(); }
    m = red[0]; __syncthreads();
    float sum = 0.f;
    #pragma unroll
    for (int i = 0; i < 2; i++) { v[i] = __expf(v[i] - m); sum += v[i]; }
    red[tid] = sum; __syncthreads();
    for (int s = 128; s > 0; s >>= 1) { if (tid < s) red[tid] += red[tid+s]; __syncthreads(); }
    float inv = 1.0f / red[0];
    #pragma unroll
    for (int i = 0; i < 2; i++) {
        int l = tid + i*256;
        if (l < LL) wv[l] = v[i] * inv;
    }
    __syncthreads();
    float acc = 0.f;
    const float* xb = g_x + (size_t)b*LL*DD;
    for (int l = 0; l < LL; l++) acc += wv[l] * xb[(size_t)l*DD + tid];
    out[b*DD + tid] = acc;
}

// ---------------- launcher ----------------
extern "C" void kernel_launch(void* const* d_in, const int* in_sizes, int n_in,
                              void* d_out, int out_size)
{
    const float* gene   = (const float*)d_in[0];
    const float* coords = (const float*)d_in[1];
    const float* w_in   = (const float*)d_in[2];
    const float* b_in   = (const float*)d_in[3];
    const float* w_cls  = (const float*)d_in[4];
    const float* b_cls  = (const float*)d_in[5];
    const float* qkv_w  = (const float*)d_in[6];
    const float* qkv_b  = (const float*)d_in[7];
    const float* ln1_g  = (const float*)d_in[8];
    const float* ln1_b  = (const float*)d_in[9];
    const float* ffn_w1 = (const float*)d_in[10];
    const float* ffn_b1 = (const float*)d_in[11];
    const float* ffn_w2 = (const float*)d_in[12];
    const float* ffn_b2 = (const float*)d_in[13];
    const float* ln2_g  = (const float*)d_in[14];
    const float* ln2_b  = (const float*)d_in[15];
    const float* th1_w  = (const float*)d_in[16];
    const float* th1_b  = (const float*)d_in[17];
    const float* bn_g   = (const float*)d_in[18];
    const float* bn_b   = (const float*)d_in[19];
    const float* th2_w  = (const float*)d_in[20];
    const float* th2_b  = (const float*)d_in[21];
    float* out = (float*)d_out;

    const int gemm_smem = 2*GSTG*4;   // 40960 B
    cudaFuncSetAttribute(k_gemm_mma, cudaFuncAttributeMaxDynamicSharedMemorySize,
                         gemm_smem);

    k_wsplit<<<dim3(768/32, 256/32, NLAYER), 256>>>(qkv_w,  256, 768,  OFF_QKV);
    k_wsplit<<<dim3(1024/32, 256/32, NLAYER), 256>>>(ffn_w1, 256, 1024, OFF_FF1);
    k_wsplit<<<dim3(256/32, 1024/32, NLAYER), 256>>>(ffn_w2, 1024, 256, OFF_FF2);

    k_input<<<MM/8, 256>>>(gene, coords, w_in, b_in, w_cls, b_cls);

    for (int l = 0; l < NLAYER; l++) {
        size_t wbase = (size_t)l*WSTRIDE;
        k_gemm_mma<<<dim3(768/128, MMP/128), 256, gemm_smem>>>(
            0, wbase + OFF_QKV, qkv_b + (size_t)l*768, 768, 256);
        k_attn<<<dim3(4, BB*HH), 256>>>();
        k_addln<<<MM/8, 256>>>(ln1_g + (size_t)l*DD, ln1_b + (size_t)l*DD, 1);
        k_gemm_mma<<<dim3(1024/128, MMP/128), 256, gemm_smem>>>(
            1, wbase + OFF_FF1, ffn_b1 + (size_t)l*FFD, 1024, 256);
        k_gemm_mma<<<dim3(256/128, MMP/128), 256, gemm_smem>>>(
            2, wbase + OFF_FF2, ffn_b2 + (size_t)l*DD, 256, 1024);
        k_addln<<<MM/8, 256>>>(ln2_g + (size_t)l*DD, ln2_b + (size_t)l*DD, (l < 3) ? 1 : 0);
    }

    k_head<<<(MM + 7)/8, 256>>>(th1_w, th1_b, bn_g, bn_b, th2_w, th2_b);
    k_pool<<<BB, 256>>>(out);
}